// round 15
// baseline (speedup 1.0000x reference)
#include <cuda_runtime.h>
#include <cuda.h>
#include <cuda_fp16.h>
#include <math.h>
#include <float.h>
#include <stdint.h>

#define BATCH 4096
#define NLAT  256
#define NCHAR 128
#define NH    1024
#define NH3   3072
#define NSTEP 64
#define LDW   1280
#define KCH   16     // physical K chunks of 64

#define PERMC(g, u) (96 * ((u) >> 5) + 32 * (g) + ((u) & 31))

// ===================== scratch =============================================
__device__ float g_Z0[BATCH * NH3];
__device__ float g_T0[NCHAR * NH3];
__device__ float g_Esw[NCHAR * NH];
__device__ float g_OutZ[BATCH * NCHAR];
__device__ float g_h1[BATCH * NH];
__device__ float g_h2[BATCH * NH];
__device__ float g_bufB[BATCH * NH3];    // gh1, permuted
__device__ int   g_c[BATCH];
__device__ unsigned g_sync[32];          // per-128-row-block gi tickets (monotone)
__device__ float g_bih0p[NH3], g_bhh0p[NH3], g_bih1p[NH3], g_bhh1p[NH3];
__device__ __align__(16) __half g_h1hi[2][BATCH * NH], g_h1lo[2][BATCH * NH];
__device__ __align__(16) __half g_h2hi[BATCH * NH], g_h2lo[BATCH * NH];
__device__ __align__(16) __half g_Whh0hi[NH3 * NH], g_Whh0lo[NH3 * NH];
__device__ __align__(16) __half g_Wih1hi[NH3 * NH], g_Wih1lo[NH3 * NH];
__device__ __align__(16) __half g_Whh1hi[NH3 * NH], g_Whh1lo[NH3 * NH];
__device__ __align__(16) __half g_Wouthi[NCHAR * NH], g_Woutlo[NCHAR * NH];

// ===================== prep 0 ==============================================
__global__ void prep0_kernel(const float* __restrict__ embed_w,
                             const float* __restrict__ b_ih0,
                             const float* __restrict__ b_hh0,
                             const float* __restrict__ b_ih1,
                             const float* __restrict__ b_hh1)
{
    int i = blockIdx.x * blockDim.x + threadIdx.x;
    if (i < BATCH) g_c[i] = 0;
    if (i < 32) g_sync[i] = 0u;
    if (i < NH3) {
        int g = i >> 10, u = i & 1023;
        int d = PERMC(g, u);
        g_bih0p[d] = b_ih0[i];
        g_bhh0p[d] = b_hh0[i];
        g_bih1p[d] = b_ih1[i];
        g_bhh1p[d] = b_hh1[i];
    }
    if (i < NCHAR * NH) {
        float v = embed_w[i];
        g_Esw[i] = v / (1.0f + expf(-v));
    }
}

// ===================== SIMT sgemm body (precompute) =========================
__device__ void sgemm_body(int K,
                           const float* __restrict__ A, int lda,
                           const float* __restrict__ B, int ldb,
                           const float* __restrict__ bias,
                           float* __restrict__ Cm, float* __restrict__ Cm2,
                           int ldc, int permB)
{
    __shared__ float As[16 * 132];
    __shared__ float Bs[16 * 132];
    const int tid = threadIdx.x;
    const int bn = blockIdx.x * 128;
    const int bm = blockIdx.y * 128;
    const int lr = tid >> 2;
    const int lk = (tid & 3) << 2;
    int n1 = bn + lr, n2 = bn + lr + 64;
    if (permB) {
        int r1 = n1 % 96, r2 = n2 % 96;
        n1 = (r1 / 32) * 1024 + (n1 / 96) * 32 + (r1 % 32);
        n2 = (r2 / 32) * 1024 + (n2 / 96) * 32 + (r2 % 32);
    }
    const float* Ap  = A + (size_t)(bm + lr) * lda + lk;
    const float* Ap2 = A + (size_t)(bm + lr + 64) * lda + lk;
    const float* Bp  = B + (size_t)n1 * ldb + lk;
    const float* Bp2 = B + (size_t)n2 * ldb + lk;
    const int tx = tid & 15;
    const int ty = tid >> 4;
    float acc[8][8];
#pragma unroll
    for (int i = 0; i < 8; i++)
#pragma unroll
        for (int j = 0; j < 8; j++) acc[i][j] = 0.0f;
    float4 pa0 = *(const float4*)Ap;
    float4 pa1 = *(const float4*)Ap2;
    float4 pb0 = *(const float4*)Bp;
    float4 pb1 = *(const float4*)Bp2;
    const int ntiles = K >> 4;
    for (int tk = 0; tk < ntiles; ++tk) {
        As[(lk + 0) * 132 + lr] = pa0.x; As[(lk + 1) * 132 + lr] = pa0.y;
        As[(lk + 2) * 132 + lr] = pa0.z; As[(lk + 3) * 132 + lr] = pa0.w;
        As[(lk + 0) * 132 + lr + 64] = pa1.x; As[(lk + 1) * 132 + lr + 64] = pa1.y;
        As[(lk + 2) * 132 + lr + 64] = pa1.z; As[(lk + 3) * 132 + lr + 64] = pa1.w;
        Bs[(lk + 0) * 132 + lr] = pb0.x; Bs[(lk + 1) * 132 + lr] = pb0.y;
        Bs[(lk + 2) * 132 + lr] = pb0.z; Bs[(lk + 3) * 132 + lr] = pb0.w;
        Bs[(lk + 0) * 132 + lr + 64] = pb1.x; Bs[(lk + 1) * 132 + lr + 64] = pb1.y;
        Bs[(lk + 2) * 132 + lr + 64] = pb1.z; Bs[(lk + 3) * 132 + lr + 64] = pb1.w;
        __syncthreads();
        if (tk + 1 < ntiles) {
            pa0 = *(const float4*)(Ap  + (tk + 1) * 16);
            pa1 = *(const float4*)(Ap2 + (tk + 1) * 16);
            pb0 = *(const float4*)(Bp  + (tk + 1) * 16);
            pb1 = *(const float4*)(Bp2 + (tk + 1) * 16);
        }
#pragma unroll
        for (int k = 0; k < 16; ++k) {
            float4 a0 = *(const float4*)&As[k * 132 + ty * 8];
            float4 a1 = *(const float4*)&As[k * 132 + ty * 8 + 4];
            float4 b0 = *(const float4*)&Bs[k * 132 + tx * 8];
            float4 b1 = *(const float4*)&Bs[k * 132 + tx * 8 + 4];
            float av[8] = {a0.x, a0.y, a0.z, a0.w, a1.x, a1.y, a1.z, a1.w};
            float bv[8] = {b0.x, b0.y, b0.z, b0.w, b1.x, b1.y, b1.z, b1.w};
#pragma unroll
            for (int i = 0; i < 8; i++)
#pragma unroll
                for (int j = 0; j < 8; j++)
                    acc[i][j] += av[i] * bv[j];
        }
        __syncthreads();
    }
    float bb[8];
#pragma unroll
    for (int j = 0; j < 8; j++) bb[j] = bias ? bias[bn + tx * 8 + j] : 0.0f;
#pragma unroll
    for (int i = 0; i < 8; i++) {
        size_t off = (size_t)(bm + ty * 8 + i) * ldc + bn + tx * 8;
        float4 v0 = make_float4(acc[i][0] + bb[0], acc[i][1] + bb[1],
                                acc[i][2] + bb[2], acc[i][3] + bb[3]);
        float4 v1 = make_float4(acc[i][4] + bb[4], acc[i][5] + bb[5],
                                acc[i][6] + bb[6], acc[i][7] + bb[7]);
        *(float4*)(Cm + off) = v0;
        *(float4*)(Cm + off + 4) = v1;
        if (Cm2) { *(float4*)(Cm2 + off) = v0; *(float4*)(Cm2 + off + 4) = v1; }
    }
}

__global__ __launch_bounds__(256, 2)
void prep_gemms(const float* __restrict__ zin,
                const float* __restrict__ w_ih0,
                const float* __restrict__ z2h_w, const float* __restrict__ z2h_b,
                const float* __restrict__ h2o_w, const float* __restrict__ h2o_b)
{
    int zz = blockIdx.z;
    if (zz == 0) {
        if (blockIdx.y != 0 || blockIdx.x >= 24) return;
        sgemm_body(NH, g_Esw, NH, w_ih0, LDW, nullptr, g_T0, nullptr, NH3, 1);
    } else if (zz == 1) {
        if (blockIdx.x >= 24) return;
        sgemm_body(NLAT, zin, NLAT, w_ih0 + NH, LDW, g_bih0p, g_Z0, nullptr, NH3, 1);
    } else if (zz == 2) {
        if (blockIdx.x != 0) return;
        sgemm_body(NLAT, zin, NLAT, h2o_w + NH, LDW, h2o_b, g_OutZ, nullptr, NCHAR, 0);
    } else {
        if (blockIdx.x >= 8) return;
        sgemm_body(NLAT, zin, NLAT, z2h_w, NLAT, z2h_b, g_h1, g_h2, NH, 0);
    }
}

// ===================== merged splits: grid (16384,1,5) ======================
__global__ void splits_kernel(const float* __restrict__ w_hh0,
                              const float* __restrict__ w_ih1,
                              const float* __restrict__ w_hh1,
                              const float* __restrict__ h2o_w)
{
    int zz = blockIdx.z;
    int i = blockIdx.x * blockDim.x + threadIdx.x;
    if (zz < 3) {
        if (i >= NH3 * NH) return;
        const float* src = (zz == 0) ? w_hh0 : (zz == 1) ? w_ih1 : w_hh1;
        __half* hi = (zz == 0) ? g_Whh0hi : (zz == 1) ? g_Wih1hi : g_Whh1hi;
        __half* lo = (zz == 0) ? g_Whh0lo : (zz == 1) ? g_Wih1lo : g_Whh1lo;
        int r = i >> 10, cc = i & 1023;
        int g = r >> 10, u = r & 1023;
        int dr = PERMC(g, u);
        float v = src[(size_t)r * NH + cc];
        __half h = __float2half_rn(v);
        hi[(size_t)dr * NH + cc] = h;
        lo[(size_t)dr * NH + cc] = __float2half_rn(v - __half2float(h));
    } else if (zz == 3) {
        if (i >= NCHAR * NH) return;
        int r = i >> 10, cc = i & 1023;
        float v = h2o_w[(size_t)r * LDW + cc];
        __half h = __float2half_rn(v);
        g_Wouthi[i] = h;
        g_Woutlo[i] = __float2half_rn(v - __half2float(h));
    } else {
        if (i >= BATCH * NH) return;
        float v = g_h1[i];
        __half h = __float2half_rn(v);
        __half lo = __float2half_rn(v - __half2float(h));
        g_h1hi[0][i] = h; g_h1lo[0][i] = lo;
        g_h2hi[i] = h;    g_h2lo[i] = lo;
    }
}

// ===================== TMA + mma.sync fp16 split GEMM core ==================
#define SMOFF(r, c) ((r) * 128 + ((((c) ^ ((r) & 7)) << 4)))

__device__ __forceinline__ uint32_t smem_u32(const void* p) {
    uint32_t a;
    asm("{ .reg .u64 t; cvta.to.shared.u64 t, %1; cvt.u32.u64 %0, t; }"
        : "=r"(a) : "l"(p));
    return a;
}
__device__ __forceinline__ void ldm_x4(uint32_t* r, uint32_t addr) {
    asm volatile("ldmatrix.sync.aligned.m8n8.x4.shared.b16 {%0,%1,%2,%3}, [%4];"
                 : "=r"(r[0]), "=r"(r[1]), "=r"(r[2]), "=r"(r[3]) : "r"(addr));
}
__device__ __forceinline__ void mma16816f(float* c, const uint32_t* a, const uint32_t* b) {
    asm volatile("mma.sync.aligned.m16n8k16.row.col.f32.f16.f16.f32 "
                 "{%0,%1,%2,%3}, {%4,%5,%6,%7}, {%8,%9}, {%0,%1,%2,%3};"
                 : "+f"(c[0]), "+f"(c[1]), "+f"(c[2]), "+f"(c[3])
                 : "r"(a[0]), "r"(a[1]), "r"(a[2]), "r"(a[3]), "r"(b[0]), "r"(b[1]));
}
__device__ __forceinline__ void tma2d(uint32_t dst, const CUtensorMap* map,
                                      int x, int y, uint32_t bar) {
    asm volatile("cp.async.bulk.tensor.2d.shared::cta.global.tile.mbarrier::complete_tx::bytes "
                 "[%0], [%1, {%2, %3}], [%4];"
                 :: "r"(dst), "l"(map), "r"(x), "r"(y), "r"(bar) : "memory");
}
#define MBARRIER_INIT(mbar, cnt) \
    asm volatile("mbarrier.init.shared.b64 [%0], %1;" \
        :: "r"((uint32_t)(mbar)), "r"((uint32_t)(cnt)) : "memory")
#define MBARRIER_INVAL(mbar) \
    asm volatile("mbarrier.inval.shared.b64 [%0];" \
        :: "r"((uint32_t)(mbar)) : "memory")
#define MBARRIER_EXPECT_TX(mbar, tx) \
    asm volatile("mbarrier.arrive.expect_tx.shared.b64 _, [%0], %1;" \
        :: "r"((uint32_t)(mbar)), "r"((uint32_t)(tx)) : "memory")
#define MBARRIER_WAIT_PARITY(mbar, par) do { \
    uint32_t _m = (uint32_t)(mbar); uint32_t _p = (uint32_t)(par); uint32_t _d; \
    asm volatile("{\n\t.reg .pred p;\n\t" \
        "mbarrier.try_wait.parity.acquire.cta.shared::cta.b64 p, [%1], %2;\n\t" \
        "selp.b32 %0, 1, 0, p;\n\t}" : "=r"(_d) : "r"(_m), "r"(_p) : "memory"); \
    if (!_d) { \
        asm volatile("{\n\t.reg .pred P1;\n\t" \
            "WL_%=:\n\t" \
            "mbarrier.try_wait.parity.acquire.cta.shared::cta.b64 P1, [%0], %1, 0x989680;\n\t" \
            "@P1 bra.uni WD_%=;\n\t" \
            "bra.uni WL_%=;\n\t" \
            "WD_%=:\n\t}" :: "r"(_m), "r"(_p) : "memory"); \
    } } while (0)

// Stage slot: [Ah | Al | Bh | Bl]; double-buffered; loads via TMA (off LSU).
template<int AT, int NB, int MT, int NT, int WMS>
__device__ __forceinline__ void mma_mainloop(
    const CUtensorMap* mAh, const CUtensorMap* mAl,
    const CUtensorMap* mBh, const CUtensorMap* mBl,
    int bm, int bn, char* smem, float (&acc)[MT][NT][4])
{
    constexpr int STB = 2 * AT * 4096 + 2 * NB * 128;
    constexpr int WNS = 8 / WMS;
    const int tid = threadIdx.x;
    const int wid = tid >> 5, l = tid & 31;
    const int wm = wid / WNS, wn = wid % WNS;
    uint32_t sbase = smem_u32(smem);
    uint32_t mb = sbase;             // 2 mbarriers @ +0, +8
    uint32_t stg = sbase + 1024;     // stage slots (1024-aligned)

#pragma unroll
    for (int mt = 0; mt < MT; ++mt)
#pragma unroll
        for (int nt = 0; nt < NT; ++nt)
#pragma unroll
            for (int e = 0; e < 4; ++e) acc[mt][nt][e] = 0.0f;

    if (tid == 0) { MBARRIER_INIT(mb, 1); MBARRIER_INIT(mb + 8, 1); }
    __syncthreads();

    auto issue = [&](int kc) {
        int s = kc & 1;
        uint32_t st = stg + s * STB;
        uint32_t bar = mb + s * 8;
        MBARRIER_EXPECT_TX(bar, STB);
        tma2d(st,                            mAh, kc * 64, bm, bar);
        tma2d(st + AT * 4096,                mAl, kc * 64, bm, bar);
        tma2d(st + 2 * AT * 4096,            mBh, kc * 64, bn, bar);
        tma2d(st + 2 * AT * 4096 + NB * 128, mBl, kc * 64, bn, bar);
    };
    if (tid == 0) { issue(0); issue(1); }

#pragma unroll 1
    for (int kc = 0; kc < KCH; ++kc) {
        int s = kc & 1;
        MBARRIER_WAIT_PARITY(mb + s * 8, (kc >> 1) & 1);

        uint32_t sAh = stg + s * STB;
        uint32_t sAl = sAh + AT * 4096;
        uint32_t sBh = sAh + 2 * AT * 4096;
        uint32_t sBl = sBh + NB * 128;
#pragma unroll
        for (int kt = 0; kt < 4; ++kt) {
            uint32_t afh[MT][4], afl[MT][4];
#pragma unroll
            for (int mt = 0; mt < MT; ++mt) {
                int row = wm * (MT * 16) + mt * 16 + (l & 15);
                int col = kt * 2 + (l >> 4);
                ldm_x4(afh[mt], sAh + SMOFF(row, col));
                ldm_x4(afl[mt], sAl + SMOFF(row, col));
            }
            uint32_t bh[NT][2], bl[NT][2];
            int g = l >> 3;
#pragma unroll
            for (int p = 0; p < NT / 2; ++p) {
                int nrow = wn * (NT * 8) + p * 16 + ((g >> 1) << 3) + (l & 7);
                int col = kt * 2 + (g & 1);
                uint32_t rr[4];
                ldm_x4(rr, sBh + SMOFF(nrow, col));
                bh[2 * p][0] = rr[0];     bh[2 * p][1] = rr[1];
                bh[2 * p + 1][0] = rr[2]; bh[2 * p + 1][1] = rr[3];
                ldm_x4(rr, sBl + SMOFF(nrow, col));
                bl[2 * p][0] = rr[0];     bl[2 * p][1] = rr[1];
                bl[2 * p + 1][0] = rr[2]; bl[2 * p + 1][1] = rr[3];
            }
#pragma unroll
            for (int mt = 0; mt < MT; ++mt)
#pragma unroll
                for (int nt = 0; nt < NT; ++nt) {
                    mma16816f(acc[mt][nt], afh[mt], bh[nt]);
                    mma16816f(acc[mt][nt], afh[mt], bl[nt]);
                    mma16816f(acc[mt][nt], afl[mt], bh[nt]);
                }
        }
        __syncthreads();           // all warps done with slot s
        if (tid == 0 && kc + 2 < KCH) issue(kc + 2);
    }
    // fully quiesced on exit: all TMA consumed, no outstanding barriers
}

// ===================== combined gh kernel: grid (32,32,2) ===================
__global__ __launch_bounds__(256, 2)
void gh_kernel(const __grid_constant__ CUtensorMap mA0h, const __grid_constant__ CUtensorMap mA0l,
               const __grid_constant__ CUtensorMap mB0h, const __grid_constant__ CUtensorMap mB0l,
               const __grid_constant__ CUtensorMap mA1h, const __grid_constant__ CUtensorMap mA1l,
               const __grid_constant__ CUtensorMap mB1h, const __grid_constant__ CUtensorMap mB1l,
               float* __restrict__ h1O, __half* __restrict__ h1hiB, __half* __restrict__ h1loB)
{
    extern __shared__ char smem[];
    const int zz = blockIdx.z;
    const int bn = blockIdx.x * 96, bm = blockIdx.y * 128;
    const int tid = threadIdx.x;
    const int wid = tid >> 5, l = tid & 31;
    const int wm = wid >> 1, wn = wid & 1;   // 4x2 warp grid

    float acc[2][6][4];
    mma_mainloop<4, 96, 2, 6, 4>(zz ? &mA1h : &mA0h, zz ? &mA1l : &mA0l,
                                 zz ? &mB1h : &mB0h, zz ? &mB1l : &mB0l,
                                 bm, bn, smem, acc);

    if (zz == 1) {
#pragma unroll
        for (int mt = 0; mt < 2; ++mt)
#pragma unroll
            for (int nt = 0; nt < 6; ++nt) {
                int row = bm + wm * 32 + mt * 16 + (l >> 2);
                int col = bn + wn * 48 + nt * 8 + ((l & 3) << 1);
                float b0 = g_bhh1p[col], b1 = g_bhh1p[col + 1];
                *(float2*)&g_bufB[(size_t)row * NH3 + col] =
                    make_float2(acc[mt][nt][0] + b0, acc[mt][nt][1] + b1);
                *(float2*)&g_bufB[(size_t)(row + 8) * NH3 + col] =
                    make_float2(acc[mt][nt][2] + b0, acc[mt][nt][3] + b1);
            }
        return;
    }

    // z=0: gates1 epilogue (stage C tile in smem)
    __syncthreads();
    float* Cs = (float*)(smem + 1024);
#pragma unroll
    for (int mt = 0; mt < 2; ++mt)
#pragma unroll
        for (int nt = 0; nt < 6; ++nt) {
            int r0 = wm * 32 + mt * 16 + (l >> 2);
            int c0 = wn * 48 + nt * 8 + ((l & 3) << 1);
            Cs[r0 * 100 + c0]           = acc[mt][nt][0];
            Cs[r0 * 100 + c0 + 1]       = acc[mt][nt][1];
            Cs[(r0 + 8) * 100 + c0]     = acc[mt][nt][2];
            Cs[(r0 + 8) * 100 + c0 + 1] = acc[mt][nt][3];
        }
    __syncthreads();

    const int ul = l;
    const int u  = bn / 3 + ul;
    float bh0 = g_bhh0p[bn + ul];
    float bh1 = g_bhh0p[bn + 32 + ul];
    float bh2 = g_bhh0p[bn + 64 + ul];
#pragma unroll 2
    for (int i = 0; i < 16; ++i) {
        int rb = wid * 16 + i;
        int b = bm + rb;
        float ghr = Cs[rb * 100 + ul] + bh0;
        float ghz = Cs[rb * 100 + 32 + ul] + bh1;
        float ghn = Cs[rb * 100 + 64 + ul] + bh2;
        const float* gp = g_Z0 + (size_t)b * NH3 + bn;
        int cb = g_c[b];
        const float* tp = g_T0 + (size_t)cb * NH3 + bn;
        float gir = gp[ul] + tp[ul];
        float giz = gp[32 + ul] + tp[32 + ul];
        float gin = gp[64 + ul] + tp[64 + ul];
        float r  = 1.0f / (1.0f + expf(-(gir + ghr)));
        float zg = 1.0f / (1.0f + expf(-(giz + ghz)));
        float nn = tanhf(gin + r * ghn);
        size_t hidx = (size_t)b * NH + u;
        float hv = h1O[hidx];
        float hn2 = (1.0f - zg) * nn + zg * hv;
        h1O[hidx] = hn2;
        __half hb = __float2half_rn(hn2);
        h1hiB[hidx] = hb;
        h1loB[hidx] = __float2half_rn(hn2 - __half2float(hb));
    }
}

// ========== gi kernel: grid 1024; last finisher per 128-row block does h2o ==
__global__ __launch_bounds__(256, 2)
void gi_kernel(const __grid_constant__ CUtensorMap mAh, const __grid_constant__ CUtensorMap mAl,
               const __grid_constant__ CUtensorMap mBh, const __grid_constant__ CUtensorMap mBl,
               const __grid_constant__ CUtensorMap oAh, const __grid_constant__ CUtensorMap oAl,
               const __grid_constant__ CUtensorMap oBh, const __grid_constant__ CUtensorMap oBl,
               float* __restrict__ out, int t)
{
    extern __shared__ char smem[];
    const int bid = blockIdx.x;
    const int bn = (bid & 31) * 96, bm = (bid >> 5) * 128;
    const int tid = threadIdx.x;
    const int wid = tid >> 5, l = tid & 31;

    {   // ---- gi role: gi1 MMA + fused gates2 -> h2, splits ----
        const int wm = wid >> 1, wn = wid & 1;   // 4x2 warp grid
        float acc[2][6][4];
        mma_mainloop<4, 96, 2, 6, 4>(&mAh, &mAl, &mBh, &mBl, bm, bn, smem, acc);

        __syncthreads();
        float* Cs = (float*)(smem + 1024);
#pragma unroll
        for (int mt = 0; mt < 2; ++mt)
#pragma unroll
            for (int nt = 0; nt < 6; ++nt) {
                int r0 = wm * 32 + mt * 16 + (l >> 2);
                int c0 = wn * 48 + nt * 8 + ((l & 3) << 1);
                Cs[r0 * 100 + c0]           = acc[mt][nt][0];
                Cs[r0 * 100 + c0 + 1]       = acc[mt][nt][1];
                Cs[(r0 + 8) * 100 + c0]     = acc[mt][nt][2];
                Cs[(r0 + 8) * 100 + c0 + 1] = acc[mt][nt][3];
            }
        __syncthreads();

        const int ul = l;
        const int u  = bn / 3 + ul;
        float bi0 = g_bih1p[bn + ul];
        float bi1 = g_bih1p[bn + 32 + ul];
        float bi2 = g_bih1p[bn + 64 + ul];
#pragma unroll 2
        for (int i = 0; i < 16; ++i) {
            int rb = wid * 16 + i;
            int b = bm + rb;
            float gir = Cs[rb * 100 + ul] + bi0;
            float giz = Cs[rb * 100 + 32 + ul] + bi1;
            float gin = Cs[rb * 100 + 64 + ul] + bi2;
            const float* gp = g_bufB + (size_t)b * NH3 + bn;
            float ghr = gp[ul], ghz = gp[32 + ul], ghn = gp[64 + ul];
            float r  = 1.0f / (1.0f + expf(-(gir + ghr)));
            float zg = 1.0f / (1.0f + expf(-(giz + ghz)));
            float nn = tanhf(gin + r * ghn);
            size_t hidx = (size_t)b * NH + u;
            float hv = g_h2[hidx];
            float hn2 = (1.0f - zg) * nn + zg * hv;
            g_h2[hidx] = hn2;
            __half hb = __float2half_rn(hn2);
            g_h2hi[hidx] = hb;
            g_h2lo[hidx] = __float2half_rn(hn2 - __half2float(hb));
        }
    }

    // ---- ticket: last finisher of this 128-row block runs h2o for it ----
    __syncthreads();
    int* flag = (int*)smem;   // reuse smem word (mainloop will reinit later)
    if (tid == 0) {
        __threadfence();
        unsigned old = atomicAdd(&g_sync[bid >> 5], 1u);
        *flag = (old == 32u * (unsigned)t + 31u) ? 1 : 0;
    }
    __syncthreads();
    if (*flag == 0) return;
    __syncthreads();   // ensure all threads read flag before smem reuse

    // ---- h2o role: 4 sequential 32-row tiles (runs in gi tail wave) ----
    const int wm2 = wid >> 2, wn2 = wid & 3;   // 2x4 warp grid
#pragma unroll 1
    for (int q = 0; q < 4; ++q) {
        int rm = bm + q * 32;
        float acc2[1][4][4];
        mma_mainloop<1, 128, 1, 4, 2>(&oAh, &oAl, &oBh, &oBl, rm, 0, smem, acc2);
        __syncthreads();

        float* lg = (float*)(smem + 1024);
#pragma unroll
        for (int nt = 0; nt < 4; ++nt) {
            int rl = wm2 * 16 + (l >> 2);
            int cl = wn2 * 32 + nt * 8 + ((l & 3) << 1);
            lg[rl * 132 + cl]           = acc2[0][nt][0];
            lg[rl * 132 + cl + 1]       = acc2[0][nt][1];
            lg[(rl + 8) * 132 + cl]     = acc2[0][nt][2];
            lg[(rl + 8) * 132 + cl + 1] = acc2[0][nt][3];
        }
        __syncthreads();

        if (tid < 32) {
            int row = rm + tid;
            const float* oz = g_OutZ + (size_t)row * NCHAR;
            float* op = out + (size_t)row * (NSTEP * NCHAR) + t * NCHAR;
            float best = -FLT_MAX;
            int bi = 0;
#pragma unroll 4
            for (int c = 0; c < NCHAR; ++c) {
                float v = lg[tid * 132 + c] + oz[c];
                op[c] = v;
                if (v > best) { best = v; bi = c; }
            }
            g_c[row] = bi;
        }
        __syncthreads();   // logits read done before next quarter's TMA reuse
    }
}

// ===================== host: tensor map encoding ============================
typedef CUresult (*encode_fn_t)(CUtensorMap*, CUtensorMapDataType, cuuint32_t, void*,
                                const cuuint64_t*, const cuuint64_t*,
                                const cuuint32_t*, const cuuint32_t*,
                                CUtensorMapInterleave, CUtensorMapSwizzle,
                                CUtensorMapL2promotion, CUtensorMapFloatOOBfill);

static encode_fn_t get_encoder() {
    static encode_fn_t fp = nullptr;
    if (!fp) {
        void* p = nullptr;
        cudaDriverEntryPointQueryResult st;
        cudaGetDriverEntryPoint("cuTensorMapEncodeTiled", &p, cudaEnableDefault, &st);
        fp = (encode_fn_t)p;
    }
    return fp;
}

static void make_map(CUtensorMap* m, void* base, uint64_t nrows, uint32_t box_rows) {
    cuuint64_t dims[2]    = {1024, nrows};
    cuuint64_t strides[1] = {2048};            // row pitch bytes (fp16 x 1024)
    cuuint32_t box[2]     = {64, box_rows};    // 64 fp16 = 128B (SW128 atom)
    cuuint32_t es[2]      = {1, 1};
    get_encoder()(m, CU_TENSOR_MAP_DATA_TYPE_UINT16, 2, base, dims, strides, box, es,
                  CU_TENSOR_MAP_INTERLEAVE_NONE, CU_TENSOR_MAP_SWIZZLE_128B,
                  CU_TENSOR_MAP_L2_PROMOTION_L2_128B, CU_TENSOR_MAP_FLOAT_OOB_FILL_NONE);
}

// ===================== launch ===============================================
extern "C" void kernel_launch(void* const* d_in, const int* in_sizes, int n_in,
                              void* d_out, int out_size)
{
    const float* z       = (const float*)d_in[0];
    const float* embed_w = (const float*)d_in[1];
    const float* z2h_w   = (const float*)d_in[2];
    const float* z2h_b   = (const float*)d_in[3];
    const float* w_ih0   = (const float*)d_in[4];
    const float* w_hh0   = (const float*)d_in[5];
    const float* b_ih0   = (const float*)d_in[6];
    const float* b_hh0   = (const float*)d_in[7];
    const float* w_ih1   = (const float*)d_in[8];
    const float* w_hh1   = (const float*)d_in[9];
    const float* b_ih1   = (const float*)d_in[10];
    const float* b_hh1   = (const float*)d_in[11];
    const float* h2o_w   = (const float*)d_in[12];
    const float* h2o_b   = (const float*)d_in[13];
    float* out = (float*)d_out;

    __half *h1hi0, *h1lo0, *h2hip, *h2lop;
    __half *Whh0h, *Whh0l, *Whh1h, *Whh1l, *Wih1h, *Wih1l, *Wouth, *Woutl;
    float* h1p;
    cudaGetSymbolAddress((void**)&h1hi0, g_h1hi);
    cudaGetSymbolAddress((void**)&h1lo0, g_h1lo);
    cudaGetSymbolAddress((void**)&h2hip, g_h2hi);
    cudaGetSymbolAddress((void**)&h2lop, g_h2lo);
    cudaGetSymbolAddress((void**)&Whh0h, g_Whh0hi);
    cudaGetSymbolAddress((void**)&Whh0l, g_Whh0lo);
    cudaGetSymbolAddress((void**)&Whh1h, g_Whh1hi);
    cudaGetSymbolAddress((void**)&Whh1l, g_Whh1lo);
    cudaGetSymbolAddress((void**)&Wih1h, g_Wih1hi);
    cudaGetSymbolAddress((void**)&Wih1l, g_Wih1lo);
    cudaGetSymbolAddress((void**)&Wouth, g_Wouthi);
    cudaGetSymbolAddress((void**)&Woutl, g_Woutlo);
    cudaGetSymbolAddress((void**)&h1p, g_h1);
    __half* h1hi1 = h1hi0 + (size_t)BATCH * NH;
    __half* h1lo1 = h1lo0 + (size_t)BATCH * NH;

    // tensor maps (host-side encode; pure CPU, capture-safe)
    static CUtensorMap mh1h[2], mh1l[2], mh2h, mh2l, mh2h32, mh2l32;
    static CUtensorMap mWhh0h, mWhh0l, mWhh1h, mWhh1l, mWih1h, mWih1l, mWouth, mWoutl;
    make_map(&mh1h[0], h1hi0, BATCH, 128);
    make_map(&mh1l[0], h1lo0, BATCH, 128);
    make_map(&mh1h[1], h1hi1, BATCH, 128);
    make_map(&mh1l[1], h1lo1, BATCH, 128);
    make_map(&mh2h,    h2hip, BATCH, 128);
    make_map(&mh2l,    h2lop, BATCH, 128);
    make_map(&mh2h32,  h2hip, BATCH, 32);
    make_map(&mh2l32,  h2lop, BATCH, 32);
    make_map(&mWhh0h,  Whh0h, NH3, 96);
    make_map(&mWhh0l,  Whh0l, NH3, 96);
    make_map(&mWhh1h,  Whh1h, NH3, 96);
    make_map(&mWhh1l,  Whh1l, NH3, 96);
    make_map(&mWih1h,  Wih1h, NH3, 96);
    make_map(&mWih1l,  Wih1l, NH3, 96);
    make_map(&mWouth,  Wouth, NCHAR, 128);
    make_map(&mWoutl,  Woutl, NCHAR, 128);

    const int smem_big = 1024 + 2 * (2 * 4 * 4096 + 2 * 96 * 128);   // 115712
    cudaFuncSetAttribute(gh_kernel, cudaFuncAttributeMaxDynamicSharedMemorySize, smem_big);
    cudaFuncSetAttribute(gi_kernel, cudaFuncAttributeMaxDynamicSharedMemorySize, smem_big);

    // ---- precompute: 3 launches ----
    prep0_kernel<<<(NCHAR * NH + 255) / 256, 256>>>(embed_w, b_ih0, b_hh0, b_ih1, b_hh1);
    prep_gemms<<<dim3(24, 32, 4), 256>>>(z, w_ih0, z2h_w, z2h_b, h2o_w, h2o_b);
    splits_kernel<<<dim3(BATCH * NH / 256, 1, 5), 256>>>(w_hh0, w_ih1, w_hh1, h2o_w);

    // ---- 64 steps, 2 launches each ----
    for (int t = 0; t < NSTEP; ++t) {
        int p = t & 1;
        __half* whi = p ? h1hi0 : h1hi1;
        __half* wlo = p ? h1lo0 : h1lo1;

        gh_kernel<<<dim3(32, 32, 2), 256, smem_big>>>(
            mh1h[p], mh1l[p], mWhh0h, mWhh0l,
            mh2h, mh2l, mWhh1h, mWhh1l,
            h1p, whi, wlo);
        gi_kernel<<<1024, 256, smem_big>>>(
            mh1h[1 - p], mh1l[1 - p], mWih1h, mWih1l,
            mh2h32, mh2l32, mWouth, mWoutl, out, t);
    }
}

// round 16
// speedup vs baseline: 1.0519x; 1.0519x over previous
#include <cuda_runtime.h>
#include <cuda.h>
#include <cuda_fp16.h>
#include <math.h>
#include <float.h>
#include <stdint.h>

#define BATCH 4096
#define NLAT  256
#define NCHAR 128
#define NH    1024
#define NH3   3072
#define NSTEP 64
#define LDW   1280
#define KCH   16     // physical K chunks of 64

#define PERMC(g, u) (96 * ((u) >> 5) + 32 * (g) + ((u) & 31))

// ===================== scratch =============================================
__device__ float g_Z0[BATCH * NH3];
__device__ float g_T0[NCHAR * NH3];
__device__ float g_Esw[NCHAR * NH];
__device__ float g_OutZ[BATCH * NCHAR];
__device__ float g_h1[BATCH * NH];
__device__ float g_h2[BATCH * NH];
__device__ float g_bufB[BATCH * NH3];    // gh1, permuted
__device__ int   g_c[BATCH];
__device__ float g_bih0p[NH3], g_bhh0p[NH3], g_bih1p[NH3], g_bhh1p[NH3];
__device__ __align__(16) __half g_h1hi[2][BATCH * NH], g_h1lo[2][BATCH * NH];
__device__ __align__(16) __half g_h2hi[BATCH * NH], g_h2lo[BATCH * NH];
__device__ __align__(16) __half g_Whh0hi[NH3 * NH], g_Whh0lo[NH3 * NH];
__device__ __align__(16) __half g_Wih1hi[NH3 * NH], g_Wih1lo[NH3 * NH];
__device__ __align__(16) __half g_Whh1hi[NH3 * NH], g_Whh1lo[NH3 * NH];
__device__ __align__(16) __half g_Wouthi[NCHAR * NH], g_Woutlo[NCHAR * NH];

// ===================== prep 0 ==============================================
__global__ void prep0_kernel(const float* __restrict__ embed_w,
                             const float* __restrict__ b_ih0,
                             const float* __restrict__ b_hh0,
                             const float* __restrict__ b_ih1,
                             const float* __restrict__ b_hh1)
{
    int i = blockIdx.x * blockDim.x + threadIdx.x;
    if (i < BATCH) g_c[i] = 0;
    if (i < NH3) {
        int g = i >> 10, u = i & 1023;
        int d = PERMC(g, u);
        g_bih0p[d] = b_ih0[i];
        g_bhh0p[d] = b_hh0[i];
        g_bih1p[d] = b_ih1[i];
        g_bhh1p[d] = b_hh1[i];
    }
    if (i < NCHAR * NH) {
        float v = embed_w[i];
        g_Esw[i] = v / (1.0f + expf(-v));
    }
}

// ===================== SIMT sgemm body (precompute) =========================
__device__ void sgemm_body(int K,
                           const float* __restrict__ A, int lda,
                           const float* __restrict__ B, int ldb,
                           const float* __restrict__ bias,
                           float* __restrict__ Cm, float* __restrict__ Cm2,
                           int ldc, int permB)
{
    __shared__ float As[16 * 132];
    __shared__ float Bs[16 * 132];
    const int tid = threadIdx.x;
    const int bn = blockIdx.x * 128;
    const int bm = blockIdx.y * 128;
    const int lr = tid >> 2;
    const int lk = (tid & 3) << 2;
    int n1 = bn + lr, n2 = bn + lr + 64;
    if (permB) {
        int r1 = n1 % 96, r2 = n2 % 96;
        n1 = (r1 / 32) * 1024 + (n1 / 96) * 32 + (r1 % 32);
        n2 = (r2 / 32) * 1024 + (n2 / 96) * 32 + (r2 % 32);
    }
    const float* Ap  = A + (size_t)(bm + lr) * lda + lk;
    const float* Ap2 = A + (size_t)(bm + lr + 64) * lda + lk;
    const float* Bp  = B + (size_t)n1 * ldb + lk;
    const float* Bp2 = B + (size_t)n2 * ldb + lk;
    const int tx = tid & 15;
    const int ty = tid >> 4;
    float acc[8][8];
#pragma unroll
    for (int i = 0; i < 8; i++)
#pragma unroll
        for (int j = 0; j < 8; j++) acc[i][j] = 0.0f;
    float4 pa0 = *(const float4*)Ap;
    float4 pa1 = *(const float4*)Ap2;
    float4 pb0 = *(const float4*)Bp;
    float4 pb1 = *(const float4*)Bp2;
    const int ntiles = K >> 4;
    for (int tk = 0; tk < ntiles; ++tk) {
        As[(lk + 0) * 132 + lr] = pa0.x; As[(lk + 1) * 132 + lr] = pa0.y;
        As[(lk + 2) * 132 + lr] = pa0.z; As[(lk + 3) * 132 + lr] = pa0.w;
        As[(lk + 0) * 132 + lr + 64] = pa1.x; As[(lk + 1) * 132 + lr + 64] = pa1.y;
        As[(lk + 2) * 132 + lr + 64] = pa1.z; As[(lk + 3) * 132 + lr + 64] = pa1.w;
        Bs[(lk + 0) * 132 + lr] = pb0.x; Bs[(lk + 1) * 132 + lr] = pb0.y;
        Bs[(lk + 2) * 132 + lr] = pb0.z; Bs[(lk + 3) * 132 + lr] = pb0.w;
        Bs[(lk + 0) * 132 + lr + 64] = pb1.x; Bs[(lk + 1) * 132 + lr + 64] = pb1.y;
        Bs[(lk + 2) * 132 + lr + 64] = pb1.z; Bs[(lk + 3) * 132 + lr + 64] = pb1.w;
        __syncthreads();
        if (tk + 1 < ntiles) {
            pa0 = *(const float4*)(Ap  + (tk + 1) * 16);
            pa1 = *(const float4*)(Ap2 + (tk + 1) * 16);
            pb0 = *(const float4*)(Bp  + (tk + 1) * 16);
            pb1 = *(const float4*)(Bp2 + (tk + 1) * 16);
        }
#pragma unroll
        for (int k = 0; k < 16; ++k) {
            float4 a0 = *(const float4*)&As[k * 132 + ty * 8];
            float4 a1 = *(const float4*)&As[k * 132 + ty * 8 + 4];
            float4 b0 = *(const float4*)&Bs[k * 132 + tx * 8];
            float4 b1 = *(const float4*)&Bs[k * 132 + tx * 8 + 4];
            float av[8] = {a0.x, a0.y, a0.z, a0.w, a1.x, a1.y, a1.z, a1.w};
            float bv[8] = {b0.x, b0.y, b0.z, b0.w, b1.x, b1.y, b1.z, b1.w};
#pragma unroll
            for (int i = 0; i < 8; i++)
#pragma unroll
                for (int j = 0; j < 8; j++)
                    acc[i][j] += av[i] * bv[j];
        }
        __syncthreads();
    }
    float bb[8];
#pragma unroll
    for (int j = 0; j < 8; j++) bb[j] = bias ? bias[bn + tx * 8 + j] : 0.0f;
#pragma unroll
    for (int i = 0; i < 8; i++) {
        size_t off = (size_t)(bm + ty * 8 + i) * ldc + bn + tx * 8;
        float4 v0 = make_float4(acc[i][0] + bb[0], acc[i][1] + bb[1],
                                acc[i][2] + bb[2], acc[i][3] + bb[3]);
        float4 v1 = make_float4(acc[i][4] + bb[4], acc[i][5] + bb[5],
                                acc[i][6] + bb[6], acc[i][7] + bb[7]);
        *(float4*)(Cm + off) = v0;
        *(float4*)(Cm + off + 4) = v1;
        if (Cm2) { *(float4*)(Cm2 + off) = v0; *(float4*)(Cm2 + off + 4) = v1; }
    }
}

__global__ __launch_bounds__(256, 2)
void prep_gemms(const float* __restrict__ zin,
                const float* __restrict__ w_ih0,
                const float* __restrict__ z2h_w, const float* __restrict__ z2h_b,
                const float* __restrict__ h2o_w, const float* __restrict__ h2o_b)
{
    int zz = blockIdx.z;
    if (zz == 0) {
        if (blockIdx.y != 0 || blockIdx.x >= 24) return;
        sgemm_body(NH, g_Esw, NH, w_ih0, LDW, nullptr, g_T0, nullptr, NH3, 1);
    } else if (zz == 1) {
        if (blockIdx.x >= 24) return;
        sgemm_body(NLAT, zin, NLAT, w_ih0 + NH, LDW, g_bih0p, g_Z0, nullptr, NH3, 1);
    } else if (zz == 2) {
        if (blockIdx.x != 0) return;
        sgemm_body(NLAT, zin, NLAT, h2o_w + NH, LDW, h2o_b, g_OutZ, nullptr, NCHAR, 0);
    } else {
        if (blockIdx.x >= 8) return;
        sgemm_body(NLAT, zin, NLAT, z2h_w, NLAT, z2h_b, g_h1, g_h2, NH, 0);
    }
}

// ===================== merged splits: grid (16384,1,5) ======================
__global__ void splits_kernel(const float* __restrict__ w_hh0,
                              const float* __restrict__ w_ih1,
                              const float* __restrict__ w_hh1,
                              const float* __restrict__ h2o_w)
{
    int zz = blockIdx.z;
    int i = blockIdx.x * blockDim.x + threadIdx.x;
    if (zz < 3) {
        if (i >= NH3 * NH) return;
        const float* src = (zz == 0) ? w_hh0 : (zz == 1) ? w_ih1 : w_hh1;
        __half* hi = (zz == 0) ? g_Whh0hi : (zz == 1) ? g_Wih1hi : g_Whh1hi;
        __half* lo = (zz == 0) ? g_Whh0lo : (zz == 1) ? g_Wih1lo : g_Whh1lo;
        int r = i >> 10, cc = i & 1023;
        int g = r >> 10, u = r & 1023;
        int dr = PERMC(g, u);
        float v = src[(size_t)r * NH + cc];
        __half h = __float2half_rn(v);
        hi[(size_t)dr * NH + cc] = h;
        lo[(size_t)dr * NH + cc] = __float2half_rn(v - __half2float(h));
    } else if (zz == 3) {
        if (i >= NCHAR * NH) return;
        int r = i >> 10, cc = i & 1023;
        float v = h2o_w[(size_t)r * LDW + cc];
        __half h = __float2half_rn(v);
        g_Wouthi[i] = h;
        g_Woutlo[i] = __float2half_rn(v - __half2float(h));
    } else {
        if (i >= BATCH * NH) return;
        float v = g_h1[i];
        __half h = __float2half_rn(v);
        __half lo = __float2half_rn(v - __half2float(h));
        g_h1hi[0][i] = h; g_h1lo[0][i] = lo;
        g_h2hi[i] = h;    g_h2lo[i] = lo;
    }
}

// ===================== TMA + mma.sync fp16 split GEMM core ==================
#define SMOFF(r, c) ((r) * 128 + ((((c) ^ ((r) & 7)) << 4)))

__device__ __forceinline__ uint32_t smem_u32(const void* p) {
    uint32_t a;
    asm("{ .reg .u64 t; cvta.to.shared.u64 t, %1; cvt.u32.u64 %0, t; }"
        : "=r"(a) : "l"(p));
    return a;
}
__device__ __forceinline__ void ldm_x4(uint32_t* r, uint32_t addr) {
    asm volatile("ldmatrix.sync.aligned.m8n8.x4.shared.b16 {%0,%1,%2,%3}, [%4];"
                 : "=r"(r[0]), "=r"(r[1]), "=r"(r[2]), "=r"(r[3]) : "r"(addr));
}
__device__ __forceinline__ void mma16816f(float* c, const uint32_t* a, const uint32_t* b) {
    asm volatile("mma.sync.aligned.m16n8k16.row.col.f32.f16.f16.f32 "
                 "{%0,%1,%2,%3}, {%4,%5,%6,%7}, {%8,%9}, {%0,%1,%2,%3};"
                 : "+f"(c[0]), "+f"(c[1]), "+f"(c[2]), "+f"(c[3])
                 : "r"(a[0]), "r"(a[1]), "r"(a[2]), "r"(a[3]), "r"(b[0]), "r"(b[1]));
}
__device__ __forceinline__ void tma2d(uint32_t dst, const CUtensorMap* map,
                                      int x, int y, uint32_t bar) {
    asm volatile("cp.async.bulk.tensor.2d.shared::cta.global.tile.mbarrier::complete_tx::bytes "
                 "[%0], [%1, {%2, %3}], [%4];"
                 :: "r"(dst), "l"(map), "r"(x), "r"(y), "r"(bar) : "memory");
}
#define MBARRIER_INIT(mbar, cnt) \
    asm volatile("mbarrier.init.shared.b64 [%0], %1;" \
        :: "r"((uint32_t)(mbar)), "r"((uint32_t)(cnt)) : "memory")
#define MBARRIER_EXPECT_TX(mbar, tx) \
    asm volatile("mbarrier.arrive.expect_tx.shared.b64 _, [%0], %1;" \
        :: "r"((uint32_t)(mbar)), "r"((uint32_t)(tx)) : "memory")
#define MBARRIER_WAIT_PARITY(mbar, par) do { \
    uint32_t _m = (uint32_t)(mbar); uint32_t _p = (uint32_t)(par); uint32_t _d; \
    asm volatile("{\n\t.reg .pred p;\n\t" \
        "mbarrier.try_wait.parity.acquire.cta.shared::cta.b64 p, [%1], %2;\n\t" \
        "selp.b32 %0, 1, 0, p;\n\t}" : "=r"(_d) : "r"(_m), "r"(_p) : "memory"); \
    if (!_d) { \
        asm volatile("{\n\t.reg .pred P1;\n\t" \
            "WL_%=:\n\t" \
            "mbarrier.try_wait.parity.acquire.cta.shared::cta.b64 P1, [%0], %1, 0x989680;\n\t" \
            "@P1 bra.uni WD_%=;\n\t" \
            "bra.uni WL_%=;\n\t" \
            "WD_%=:\n\t}" :: "r"(_m), "r"(_p) : "memory"); \
    } } while (0)

// Stage slot: [Ah | Al | Bh | Bl]; double-buffered; loads via TMA (off LSU).
template<int AT, int NB, int MT, int NT, int WMS>
__device__ __forceinline__ void mma_mainloop(
    const CUtensorMap* mAh, const CUtensorMap* mAl,
    const CUtensorMap* mBh, const CUtensorMap* mBl,
    int bm, int bn, char* smem, float (&acc)[MT][NT][4])
{
    constexpr int STB = 2 * AT * 4096 + 2 * NB * 128;
    constexpr int WNS = 8 / WMS;
    const int tid = threadIdx.x;
    const int wid = tid >> 5, l = tid & 31;
    const int wm = wid / WNS, wn = wid % WNS;
    uint32_t sbase = smem_u32(smem);
    uint32_t mb = sbase;             // 2 mbarriers @ +0, +8
    uint32_t stg = sbase + 1024;     // stage slots (1024-aligned)

#pragma unroll
    for (int mt = 0; mt < MT; ++mt)
#pragma unroll
        for (int nt = 0; nt < NT; ++nt)
#pragma unroll
            for (int e = 0; e < 4; ++e) acc[mt][nt][e] = 0.0f;

    if (tid == 0) { MBARRIER_INIT(mb, 1); MBARRIER_INIT(mb + 8, 1); }
    __syncthreads();

    auto issue = [&](int kc) {
        int s = kc & 1;
        uint32_t st = stg + s * STB;
        uint32_t bar = mb + s * 8;
        MBARRIER_EXPECT_TX(bar, STB);
        tma2d(st,                            mAh, kc * 64, bm, bar);
        tma2d(st + AT * 4096,                mAl, kc * 64, bm, bar);
        tma2d(st + 2 * AT * 4096,            mBh, kc * 64, bn, bar);
        tma2d(st + 2 * AT * 4096 + NB * 128, mBl, kc * 64, bn, bar);
    };
    if (tid == 0) { issue(0); issue(1); }

#pragma unroll 1
    for (int kc = 0; kc < KCH; ++kc) {
        int s = kc & 1;
        MBARRIER_WAIT_PARITY(mb + s * 8, (kc >> 1) & 1);

        uint32_t sAh = stg + s * STB;
        uint32_t sAl = sAh + AT * 4096;
        uint32_t sBh = sAh + 2 * AT * 4096;
        uint32_t sBl = sBh + NB * 128;
#pragma unroll
        for (int kt = 0; kt < 4; ++kt) {
            uint32_t afh[MT][4], afl[MT][4];
#pragma unroll
            for (int mt = 0; mt < MT; ++mt) {
                int row = wm * (MT * 16) + mt * 16 + (l & 15);
                int col = kt * 2 + (l >> 4);
                ldm_x4(afh[mt], sAh + SMOFF(row, col));
                ldm_x4(afl[mt], sAl + SMOFF(row, col));
            }
            uint32_t bh[NT][2], bl[NT][2];
            int g = l >> 3;
#pragma unroll
            for (int p = 0; p < NT / 2; ++p) {
                int nrow = wn * (NT * 8) + p * 16 + ((g >> 1) << 3) + (l & 7);
                int col = kt * 2 + (g & 1);
                uint32_t rr[4];
                ldm_x4(rr, sBh + SMOFF(nrow, col));
                bh[2 * p][0] = rr[0];     bh[2 * p][1] = rr[1];
                bh[2 * p + 1][0] = rr[2]; bh[2 * p + 1][1] = rr[3];
                ldm_x4(rr, sBl + SMOFF(nrow, col));
                bl[2 * p][0] = rr[0];     bl[2 * p][1] = rr[1];
                bl[2 * p + 1][0] = rr[2]; bl[2 * p + 1][1] = rr[3];
            }
#pragma unroll
            for (int mt = 0; mt < MT; ++mt)
#pragma unroll
                for (int nt = 0; nt < NT; ++nt) {
                    mma16816f(acc[mt][nt], afh[mt], bh[nt]);
                    mma16816f(acc[mt][nt], afh[mt], bl[nt]);
                    mma16816f(acc[mt][nt], afl[mt], bh[nt]);
                }
        }
        __syncthreads();           // all warps done with slot s
        if (tid == 0 && kc + 2 < KCH) issue(kc + 2);
    }
}

// ===================== gh0 kernel: grid (32,32), fused gates1 ===============
__global__ __launch_bounds__(256, 2)
void gh0_kernel(const __grid_constant__ CUtensorMap mAh, const __grid_constant__ CUtensorMap mAl,
                const __grid_constant__ CUtensorMap mBh, const __grid_constant__ CUtensorMap mBl,
                float* __restrict__ h1O, __half* __restrict__ h1hiB, __half* __restrict__ h1loB)
{
    extern __shared__ char smem[];
    const int bn = blockIdx.x * 96, bm = blockIdx.y * 128;
    const int tid = threadIdx.x;
    const int wid = tid >> 5, l = tid & 31;
    const int wm = wid >> 1, wn = wid & 1;   // 4x2 warp grid

    float acc[2][6][4];
    mma_mainloop<4, 96, 2, 6, 4>(&mAh, &mAl, &mBh, &mBl, bm, bn, smem, acc);

    __syncthreads();
    float* Cs = (float*)(smem + 1024);
#pragma unroll
    for (int mt = 0; mt < 2; ++mt)
#pragma unroll
        for (int nt = 0; nt < 6; ++nt) {
            int r0 = wm * 32 + mt * 16 + (l >> 2);
            int c0 = wn * 48 + nt * 8 + ((l & 3) << 1);
            Cs[r0 * 100 + c0]           = acc[mt][nt][0];
            Cs[r0 * 100 + c0 + 1]       = acc[mt][nt][1];
            Cs[(r0 + 8) * 100 + c0]     = acc[mt][nt][2];
            Cs[(r0 + 8) * 100 + c0 + 1] = acc[mt][nt][3];
        }
    __syncthreads();

    const int ul = l;
    const int u  = bn / 3 + ul;
    float bh0 = g_bhh0p[bn + ul];
    float bh1 = g_bhh0p[bn + 32 + ul];
    float bh2 = g_bhh0p[bn + 64 + ul];
#pragma unroll 2
    for (int i = 0; i < 16; ++i) {
        int rb = wid * 16 + i;
        int b = bm + rb;
        float ghr = Cs[rb * 100 + ul] + bh0;
        float ghz = Cs[rb * 100 + 32 + ul] + bh1;
        float ghn = Cs[rb * 100 + 64 + ul] + bh2;
        const float* gp = g_Z0 + (size_t)b * NH3 + bn;
        int cb = g_c[b];
        const float* tp = g_T0 + (size_t)cb * NH3 + bn;
        float gir = gp[ul] + tp[ul];
        float giz = gp[32 + ul] + tp[32 + ul];
        float gin = gp[64 + ul] + tp[64 + ul];
        float r  = 1.0f / (1.0f + expf(-(gir + ghr)));
        float zg = 1.0f / (1.0f + expf(-(giz + ghz)));
        float nn = tanhf(gin + r * ghn);
        size_t hidx = (size_t)b * NH + u;
        float hv = h1O[hidx];
        float hn2 = (1.0f - zg) * nn + zg * hv;
        h1O[hidx] = hn2;
        __half hb = __float2half_rn(hn2);
        h1hiB[hidx] = hb;
        h1loB[hidx] = __float2half_rn(hn2 - __half2float(hb));
    }
}

// ===================== gi kernel: grid (32,32), fused gates2 ================
__global__ __launch_bounds__(256, 2)
void gi_kernel(const __grid_constant__ CUtensorMap mAh, const __grid_constant__ CUtensorMap mAl,
               const __grid_constant__ CUtensorMap mBh, const __grid_constant__ CUtensorMap mBl)
{
    extern __shared__ char smem[];
    const int bn = blockIdx.x * 96, bm = blockIdx.y * 128;
    const int tid = threadIdx.x;
    const int wid = tid >> 5, l = tid & 31;
    const int wm = wid >> 1, wn = wid & 1;
    float acc[2][6][4];
    mma_mainloop<4, 96, 2, 6, 4>(&mAh, &mAl, &mBh, &mBl, bm, bn, smem, acc);

    __syncthreads();
    float* Cs = (float*)(smem + 1024);
#pragma unroll
    for (int mt = 0; mt < 2; ++mt)
#pragma unroll
        for (int nt = 0; nt < 6; ++nt) {
            int r0 = wm * 32 + mt * 16 + (l >> 2);
            int c0 = wn * 48 + nt * 8 + ((l & 3) << 1);
            Cs[r0 * 100 + c0]           = acc[mt][nt][0];
            Cs[r0 * 100 + c0 + 1]       = acc[mt][nt][1];
            Cs[(r0 + 8) * 100 + c0]     = acc[mt][nt][2];
            Cs[(r0 + 8) * 100 + c0 + 1] = acc[mt][nt][3];
        }
    __syncthreads();

    const int ul = l;
    const int u  = bn / 3 + ul;
    float bi0 = g_bih1p[bn + ul];
    float bi1 = g_bih1p[bn + 32 + ul];
    float bi2 = g_bih1p[bn + 64 + ul];
#pragma unroll 2
    for (int i = 0; i < 16; ++i) {
        int rb = wid * 16 + i;
        int b = bm + rb;
        float gir = Cs[rb * 100 + ul] + bi0;
        float giz = Cs[rb * 100 + 32 + ul] + bi1;
        float gin = Cs[rb * 100 + 64 + ul] + bi2;
        const float* gp = g_bufB + (size_t)b * NH3 + bn;
        float ghr = gp[ul], ghz = gp[32 + ul], ghn = gp[64 + ul];
        float r  = 1.0f / (1.0f + expf(-(gir + ghr)));
        float zg = 1.0f / (1.0f + expf(-(giz + ghz)));
        float nn = tanhf(gin + r * ghn);
        size_t hidx = (size_t)b * NH + u;
        float hv = g_h2[hidx];
        float hn2 = (1.0f - zg) * nn + zg * hv;
        g_h2[hidx] = hn2;
        __half hb = __float2half_rn(hn2);
        g_h2hi[hidx] = hb;
        g_h2lo[hidx] = __float2half_rn(hn2 - __half2float(hb));
    }
}

// ========== gh1(t+1) ∥ h2o(t): grid 1152; independent roles, no sync ========
__global__ __launch_bounds__(256, 2)
void gh1_h2o_kernel(const __grid_constant__ CUtensorMap gAh, const __grid_constant__ CUtensorMap gAl,
                    const __grid_constant__ CUtensorMap gBh, const __grid_constant__ CUtensorMap gBl,
                    const __grid_constant__ CUtensorMap oAh, const __grid_constant__ CUtensorMap oAl,
                    const __grid_constant__ CUtensorMap oBh, const __grid_constant__ CUtensorMap oBl,
                    float* __restrict__ out, int t)
{
    extern __shared__ char smem[];
    const int bid = blockIdx.x;
    const int tid = threadIdx.x;
    const int wid = tid >> 5, l = tid & 31;

    if (bid < 1024) {
        // ---- gh1 role: gh1 = h2 @ Whh1^T + bhh1p -> bufB (for NEXT step) ----
        const int bn = (bid & 31) * 96, bm = (bid >> 5) * 128;
        const int wm = wid >> 1, wn = wid & 1;
        float acc[2][6][4];
        mma_mainloop<4, 96, 2, 6, 4>(&gAh, &gAl, &gBh, &gBl, bm, bn, smem, acc);
#pragma unroll
        for (int mt = 0; mt < 2; ++mt)
#pragma unroll
            for (int nt = 0; nt < 6; ++nt) {
                int row = bm + wm * 32 + mt * 16 + (l >> 2);
                int col = bn + wn * 48 + nt * 8 + ((l & 3) << 1);
                float b0 = g_bhh1p[col], b1 = g_bhh1p[col + 1];
                *(float2*)&g_bufB[(size_t)row * NH3 + col] =
                    make_float2(acc[mt][nt][0] + b0, acc[mt][nt][1] + b1);
                *(float2*)&g_bufB[(size_t)(row + 8) * NH3 + col] =
                    make_float2(acc[mt][nt][2] + b0, acc[mt][nt][3] + b1);
            }
    } else {
        // ---- h2o role: logits/argmax for CURRENT step (skip on prologue) ----
        if (t < 0) return;
        const int bm = (bid - 1024) * 32;
        const int wm = wid >> 2, wn = wid & 3;   // 2x4 warp grid
        float acc[1][4][4];
        mma_mainloop<1, 128, 1, 4, 2>(&oAh, &oAl, &oBh, &oBl, bm, 0, smem, acc);
        __syncthreads();

        float* lg = (float*)(smem + 1024);
#pragma unroll
        for (int nt = 0; nt < 4; ++nt) {
            int rl = wm * 16 + (l >> 2);
            int cl = wn * 32 + nt * 8 + ((l & 3) << 1);
            lg[rl * 132 + cl]           = acc[0][nt][0];
            lg[rl * 132 + cl + 1]       = acc[0][nt][1];
            lg[(rl + 8) * 132 + cl]     = acc[0][nt][2];
            lg[(rl + 8) * 132 + cl + 1] = acc[0][nt][3];
        }
        __syncthreads();

        if (tid < 32) {
            int row = bm + tid;
            const float* oz = g_OutZ + (size_t)row * NCHAR;
            float* op = out + (size_t)row * (NSTEP * NCHAR) + t * NCHAR;
            float best = -FLT_MAX;
            int bi = 0;
#pragma unroll 4
            for (int c = 0; c < NCHAR; ++c) {
                float v = lg[tid * 132 + c] + oz[c];
                op[c] = v;
                if (v > best) { best = v; bi = c; }
            }
            g_c[row] = bi;
        }
    }
}

// ===================== host: tensor map encoding ============================
typedef CUresult (*encode_fn_t)(CUtensorMap*, CUtensorMapDataType, cuuint32_t, void*,
                                const cuuint64_t*, const cuuint64_t*,
                                const cuuint32_t*, const cuuint32_t*,
                                CUtensorMapInterleave, CUtensorMapSwizzle,
                                CUtensorMapL2promotion, CUtensorMapFloatOOBfill);

static encode_fn_t get_encoder() {
    static encode_fn_t fp = nullptr;
    if (!fp) {
        void* p = nullptr;
        cudaDriverEntryPointQueryResult st;
        cudaGetDriverEntryPoint("cuTensorMapEncodeTiled", &p, cudaEnableDefault, &st);
        fp = (encode_fn_t)p;
    }
    return fp;
}

static void make_map(CUtensorMap* m, void* base, uint64_t nrows, uint32_t box_rows) {
    cuuint64_t dims[2]    = {1024, nrows};
    cuuint64_t strides[1] = {2048};            // row pitch bytes (fp16 x 1024)
    cuuint32_t box[2]     = {64, box_rows};    // 64 fp16 = 128B (SW128 atom)
    cuuint32_t es[2]      = {1, 1};
    get_encoder()(m, CU_TENSOR_MAP_DATA_TYPE_UINT16, 2, base, dims, strides, box, es,
                  CU_TENSOR_MAP_INTERLEAVE_NONE, CU_TENSOR_MAP_SWIZZLE_128B,
                  CU_TENSOR_MAP_L2_PROMOTION_L2_128B, CU_TENSOR_MAP_FLOAT_OOB_FILL_NONE);
}

// ===================== launch ===============================================
extern "C" void kernel_launch(void* const* d_in, const int* in_sizes, int n_in,
                              void* d_out, int out_size)
{
    const float* z       = (const float*)d_in[0];
    const float* embed_w = (const float*)d_in[1];
    const float* z2h_w   = (const float*)d_in[2];
    const float* z2h_b   = (const float*)d_in[3];
    const float* w_ih0   = (const float*)d_in[4];
    const float* w_hh0   = (const float*)d_in[5];
    const float* b_ih0   = (const float*)d_in[6];
    const float* b_hh0   = (const float*)d_in[7];
    const float* w_ih1   = (const float*)d_in[8];
    const float* w_hh1   = (const float*)d_in[9];
    const float* b_ih1   = (const float*)d_in[10];
    const float* b_hh1   = (const float*)d_in[11];
    const float* h2o_w   = (const float*)d_in[12];
    const float* h2o_b   = (const float*)d_in[13];
    float* out = (float*)d_out;

    __half *h1hi0, *h1lo0, *h2hip, *h2lop;
    __half *Whh0h, *Whh0l, *Whh1h, *Whh1l, *Wih1h, *Wih1l, *Wouth, *Woutl;
    float* h1p;
    cudaGetSymbolAddress((void**)&h1hi0, g_h1hi);
    cudaGetSymbolAddress((void**)&h1lo0, g_h1lo);
    cudaGetSymbolAddress((void**)&h2hip, g_h2hi);
    cudaGetSymbolAddress((void**)&h2lop, g_h2lo);
    cudaGetSymbolAddress((void**)&Whh0h, g_Whh0hi);
    cudaGetSymbolAddress((void**)&Whh0l, g_Whh0lo);
    cudaGetSymbolAddress((void**)&Whh1h, g_Whh1hi);
    cudaGetSymbolAddress((void**)&Whh1l, g_Whh1lo);
    cudaGetSymbolAddress((void**)&Wih1h, g_Wih1hi);
    cudaGetSymbolAddress((void**)&Wih1l, g_Wih1lo);
    cudaGetSymbolAddress((void**)&Wouth, g_Wouthi);
    cudaGetSymbolAddress((void**)&Woutl, g_Woutlo);
    cudaGetSymbolAddress((void**)&h1p, g_h1);
    __half* h1hi1 = h1hi0 + (size_t)BATCH * NH;
    __half* h1lo1 = h1lo0 + (size_t)BATCH * NH;

    // tensor maps (host-side encode; pure CPU, capture-safe)
    static CUtensorMap mh1h[2], mh1l[2], mh2h, mh2l, mh2h32, mh2l32;
    static CUtensorMap mWhh0h, mWhh0l, mWhh1h, mWhh1l, mWih1h, mWih1l, mWouth, mWoutl;
    make_map(&mh1h[0], h1hi0, BATCH, 128);
    make_map(&mh1l[0], h1lo0, BATCH, 128);
    make_map(&mh1h[1], h1hi1, BATCH, 128);
    make_map(&mh1l[1], h1lo1, BATCH, 128);
    make_map(&mh2h,    h2hip, BATCH, 128);
    make_map(&mh2l,    h2lop, BATCH, 128);
    make_map(&mh2h32,  h2hip, BATCH, 32);
    make_map(&mh2l32,  h2lop, BATCH, 32);
    make_map(&mWhh0h,  Whh0h, NH3, 96);
    make_map(&mWhh0l,  Whh0l, NH3, 96);
    make_map(&mWhh1h,  Whh1h, NH3, 96);
    make_map(&mWhh1l,  Whh1l, NH3, 96);
    make_map(&mWih1h,  Wih1h, NH3, 96);
    make_map(&mWih1l,  Wih1l, NH3, 96);
    make_map(&mWouth,  Wouth, NCHAR, 128);
    make_map(&mWoutl,  Woutl, NCHAR, 128);

    const int smem_big = 1024 + 2 * (2 * 4 * 4096 + 2 * 96 * 128);   // 115712
    cudaFuncSetAttribute(gh0_kernel, cudaFuncAttributeMaxDynamicSharedMemorySize, smem_big);
    cudaFuncSetAttribute(gi_kernel, cudaFuncAttributeMaxDynamicSharedMemorySize, smem_big);
    cudaFuncSetAttribute(gh1_h2o_kernel, cudaFuncAttributeMaxDynamicSharedMemorySize, smem_big);

    // ---- precompute: 3 launches ----
    prep0_kernel<<<(NCHAR * NH + 255) / 256, 256>>>(embed_w, b_ih0, b_hh0, b_ih1, b_hh1);
    prep_gemms<<<dim3(24, 32, 4), 256>>>(z, w_ih0, z2h_w, z2h_b, h2o_w, h2o_b);
    splits_kernel<<<dim3(BATCH * NH / 256, 1, 5), 256>>>(w_hh0, w_ih1, w_hh1, h2o_w);

    // ---- prologue: gh1(0) from initial h2 (h2o part skipped via t=-1) ----
    gh1_h2o_kernel<<<1152, 256, smem_big>>>(
        mh2h, mh2l, mWhh1h, mWhh1l,
        mh2h32, mh2l32, mWouth, mWoutl, out, -1);

    // ---- 64 steps, 3 launches each ----
    for (int t = 0; t < NSTEP; ++t) {
        int p = t & 1;
        __half* whi = p ? h1hi0 : h1hi1;
        __half* wlo = p ? h1lo0 : h1lo1;

        // gh0(t) + gates1 -> h1 (new parity)
        gh0_kernel<<<dim3(32, 32), 256, smem_big>>>(
            mh1h[p], mh1l[p], mWhh0h, mWhh0l, h1p, whi, wlo);
        // gi(t) + gates2 -> h2, splits (consumes bufB written at step t-1)
        gi_kernel<<<dim3(32, 32), 256, smem_big>>>(
            mh1h[1 - p], mh1l[1 - p], mWih1h, mWih1l);
        // gh1(t+1) [writes bufB] ∥ h2o(t) [writes out, g_c]
        gh1_h2o_kernel<<<1152, 256, smem_big>>>(
            mh2h, mh2l, mWhh1h, mWhh1l,
            mh2h32, mh2l32, mWouth, mWoutl, out, t);
    }
}

// round 17
// speedup vs baseline: 1.1775x; 1.1194x over previous
#include <cuda_runtime.h>
#include <cuda.h>
#include <cuda_fp16.h>
#include <math.h>
#include <float.h>
#include <stdint.h>

#define BATCH 4096
#define NLAT  256
#define NCHAR 128
#define NH    1024
#define NH3   3072
#define NSTEP 64
#define LDW   1280
#define KCH   16     // physical K chunks of 64

#define PERMC(g, u) (96 * ((u) >> 5) + 32 * (g) + ((u) & 31))

// ===================== scratch =============================================
__device__ float g_Z0[BATCH * NH3];
__device__ float g_T0[NCHAR * NH3];
__device__ float g_Esw[NCHAR * NH];
__device__ float g_OutZ[BATCH * NCHAR];
__device__ float g_h1[BATCH * NH];
__device__ float g_h2[BATCH * NH];
__device__ float g_bufB[BATCH * NH3];    // gh1, permuted
__device__ int   g_c[BATCH];
__device__ unsigned g_sync[4];           // h2o completion counter (monotone)
__device__ float g_bih0p[NH3], g_bhh0p[NH3], g_bih1p[NH3], g_bhh1p[NH3];
__device__ __align__(16) __half g_h1hi[2][BATCH * NH], g_h1lo[2][BATCH * NH];
__device__ __align__(16) __half g_h2hi[BATCH * NH], g_h2lo[BATCH * NH];
__device__ __align__(16) __half g_Whh0hi[NH3 * NH], g_Whh0lo[NH3 * NH];
__device__ __align__(16) __half g_Wih1hi[NH3 * NH], g_Wih1lo[NH3 * NH];
__device__ __align__(16) __half g_Whh1hi[NH3 * NH], g_Whh1lo[NH3 * NH];
__device__ __align__(16) __half g_Wouthi[NCHAR * NH], g_Woutlo[NCHAR * NH];

// ===================== prep 0 ==============================================
__global__ void prep0_kernel(const float* __restrict__ embed_w,
                             const float* __restrict__ b_ih0,
                             const float* __restrict__ b_hh0,
                             const float* __restrict__ b_ih1,
                             const float* __restrict__ b_hh1)
{
    int i = blockIdx.x * blockDim.x + threadIdx.x;
    if (i < BATCH) g_c[i] = 0;
    if (i < 4) g_sync[i] = 0u;
    if (i < NH3) {
        int g = i >> 10, u = i & 1023;
        int d = PERMC(g, u);
        g_bih0p[d] = b_ih0[i];
        g_bhh0p[d] = b_hh0[i];
        g_bih1p[d] = b_ih1[i];
        g_bhh1p[d] = b_hh1[i];
    }
    if (i < NCHAR * NH) {
        float v = embed_w[i];
        g_Esw[i] = v / (1.0f + expf(-v));
    }
}

// ===================== SIMT sgemm body (precompute) =========================
__device__ void sgemm_body(int K,
                           const float* __restrict__ A, int lda,
                           const float* __restrict__ B, int ldb,
                           const float* __restrict__ bias,
                           float* __restrict__ Cm, float* __restrict__ Cm2,
                           int ldc, int permB)
{
    __shared__ float As[16 * 132];
    __shared__ float Bs[16 * 132];
    const int tid = threadIdx.x;
    const int bn = blockIdx.x * 128;
    const int bm = blockIdx.y * 128;
    const int lr = tid >> 2;
    const int lk = (tid & 3) << 2;
    int n1 = bn + lr, n2 = bn + lr + 64;
    if (permB) {
        int r1 = n1 % 96, r2 = n2 % 96;
        n1 = (r1 / 32) * 1024 + (n1 / 96) * 32 + (r1 % 32);
        n2 = (r2 / 32) * 1024 + (n2 / 96) * 32 + (r2 % 32);
    }
    const float* Ap  = A + (size_t)(bm + lr) * lda + lk;
    const float* Ap2 = A + (size_t)(bm + lr + 64) * lda + lk;
    const float* Bp  = B + (size_t)n1 * ldb + lk;
    const float* Bp2 = B + (size_t)n2 * ldb + lk;
    const int tx = tid & 15;
    const int ty = tid >> 4;
    float acc[8][8];
#pragma unroll
    for (int i = 0; i < 8; i++)
#pragma unroll
        for (int j = 0; j < 8; j++) acc[i][j] = 0.0f;
    float4 pa0 = *(const float4*)Ap;
    float4 pa1 = *(const float4*)Ap2;
    float4 pb0 = *(const float4*)Bp;
    float4 pb1 = *(const float4*)Bp2;
    const int ntiles = K >> 4;
    for (int tk = 0; tk < ntiles; ++tk) {
        As[(lk + 0) * 132 + lr] = pa0.x; As[(lk + 1) * 132 + lr] = pa0.y;
        As[(lk + 2) * 132 + lr] = pa0.z; As[(lk + 3) * 132 + lr] = pa0.w;
        As[(lk + 0) * 132 + lr + 64] = pa1.x; As[(lk + 1) * 132 + lr + 64] = pa1.y;
        As[(lk + 2) * 132 + lr + 64] = pa1.z; As[(lk + 3) * 132 + lr + 64] = pa1.w;
        Bs[(lk + 0) * 132 + lr] = pb0.x; Bs[(lk + 1) * 132 + lr] = pb0.y;
        Bs[(lk + 2) * 132 + lr] = pb0.z; Bs[(lk + 3) * 132 + lr] = pb0.w;
        Bs[(lk + 0) * 132 + lr + 64] = pb1.x; Bs[(lk + 1) * 132 + lr + 64] = pb1.y;
        Bs[(lk + 2) * 132 + lr + 64] = pb1.z; Bs[(lk + 3) * 132 + lr + 64] = pb1.w;
        __syncthreads();
        if (tk + 1 < ntiles) {
            pa0 = *(const float4*)(Ap  + (tk + 1) * 16);
            pa1 = *(const float4*)(Ap2 + (tk + 1) * 16);
            pb0 = *(const float4*)(Bp  + (tk + 1) * 16);
            pb1 = *(const float4*)(Bp2 + (tk + 1) * 16);
        }
#pragma unroll
        for (int k = 0; k < 16; ++k) {
            float4 a0 = *(const float4*)&As[k * 132 + ty * 8];
            float4 a1 = *(const float4*)&As[k * 132 + ty * 8 + 4];
            float4 b0 = *(const float4*)&Bs[k * 132 + tx * 8];
            float4 b1 = *(const float4*)&Bs[k * 132 + tx * 8 + 4];
            float av[8] = {a0.x, a0.y, a0.z, a0.w, a1.x, a1.y, a1.z, a1.w};
            float bv[8] = {b0.x, b0.y, b0.z, b0.w, b1.x, b1.y, b1.z, b1.w};
#pragma unroll
            for (int i = 0; i < 8; i++)
#pragma unroll
                for (int j = 0; j < 8; j++)
                    acc[i][j] += av[i] * bv[j];
        }
        __syncthreads();
    }
    float bb[8];
#pragma unroll
    for (int j = 0; j < 8; j++) bb[j] = bias ? bias[bn + tx * 8 + j] : 0.0f;
#pragma unroll
    for (int i = 0; i < 8; i++) {
        size_t off = (size_t)(bm + ty * 8 + i) * ldc + bn + tx * 8;
        float4 v0 = make_float4(acc[i][0] + bb[0], acc[i][1] + bb[1],
                                acc[i][2] + bb[2], acc[i][3] + bb[3]);
        float4 v1 = make_float4(acc[i][4] + bb[4], acc[i][5] + bb[5],
                                acc[i][6] + bb[6], acc[i][7] + bb[7]);
        *(float4*)(Cm + off) = v0;
        *(float4*)(Cm + off + 4) = v1;
        if (Cm2) { *(float4*)(Cm2 + off) = v0; *(float4*)(Cm2 + off + 4) = v1; }
    }
}

__global__ __launch_bounds__(256, 2)
void prep_gemms(const float* __restrict__ zin,
                const float* __restrict__ w_ih0,
                const float* __restrict__ z2h_w, const float* __restrict__ z2h_b,
                const float* __restrict__ h2o_w, const float* __restrict__ h2o_b)
{
    int zz = blockIdx.z;
    if (zz == 0) {
        if (blockIdx.y != 0 || blockIdx.x >= 24) return;
        sgemm_body(NH, g_Esw, NH, w_ih0, LDW, nullptr, g_T0, nullptr, NH3, 1);
    } else if (zz == 1) {
        if (blockIdx.x >= 24) return;
        sgemm_body(NLAT, zin, NLAT, w_ih0 + NH, LDW, g_bih0p, g_Z0, nullptr, NH3, 1);
    } else if (zz == 2) {
        if (blockIdx.x != 0) return;
        sgemm_body(NLAT, zin, NLAT, h2o_w + NH, LDW, h2o_b, g_OutZ, nullptr, NCHAR, 0);
    } else {
        if (blockIdx.x >= 8) return;
        sgemm_body(NLAT, zin, NLAT, z2h_w, NLAT, z2h_b, g_h1, g_h2, NH, 0);
    }
}

// ===================== merged splits: grid (16384,1,5) ======================
__global__ void splits_kernel(const float* __restrict__ w_hh0,
                              const float* __restrict__ w_ih1,
                              const float* __restrict__ w_hh1,
                              const float* __restrict__ h2o_w)
{
    int zz = blockIdx.z;
    int i = blockIdx.x * blockDim.x + threadIdx.x;
    if (zz < 3) {
        if (i >= NH3 * NH) return;
        const float* src = (zz == 0) ? w_hh0 : (zz == 1) ? w_ih1 : w_hh1;
        __half* hi = (zz == 0) ? g_Whh0hi : (zz == 1) ? g_Wih1hi : g_Whh1hi;
        __half* lo = (zz == 0) ? g_Whh0lo : (zz == 1) ? g_Wih1lo : g_Whh1lo;
        int r = i >> 10, cc = i & 1023;
        int g = r >> 10, u = r & 1023;
        int dr = PERMC(g, u);
        float v = src[(size_t)r * NH + cc];
        __half h = __float2half_rn(v);
        hi[(size_t)dr * NH + cc] = h;
        lo[(size_t)dr * NH + cc] = __float2half_rn(v - __half2float(h));
    } else if (zz == 3) {
        if (i >= NCHAR * NH) return;
        int r = i >> 10, cc = i & 1023;
        float v = h2o_w[(size_t)r * LDW + cc];
        __half h = __float2half_rn(v);
        g_Wouthi[i] = h;
        g_Woutlo[i] = __float2half_rn(v - __half2float(h));
    } else {
        if (i >= BATCH * NH) return;
        float v = g_h1[i];
        __half h = __float2half_rn(v);
        __half lo = __float2half_rn(v - __half2float(h));
        g_h1hi[0][i] = h; g_h1lo[0][i] = lo;
        g_h2hi[i] = h;    g_h2lo[i] = lo;
    }
}

// ===================== TMA + mma.sync fp16 split GEMM core ==================
#define SMOFF(r, c) ((r) * 128 + ((((c) ^ ((r) & 7)) << 4)))

__device__ __forceinline__ uint32_t smem_u32(const void* p) {
    uint32_t a;
    asm("{ .reg .u64 t; cvta.to.shared.u64 t, %1; cvt.u32.u64 %0, t; }"
        : "=r"(a) : "l"(p));
    return a;
}
__device__ __forceinline__ void ldm_x4(uint32_t* r, uint32_t addr) {
    asm volatile("ldmatrix.sync.aligned.m8n8.x4.shared.b16 {%0,%1,%2,%3}, [%4];"
                 : "=r"(r[0]), "=r"(r[1]), "=r"(r[2]), "=r"(r[3]) : "r"(addr));
}
__device__ __forceinline__ void mma16816f(float* c, const uint32_t* a, const uint32_t* b) {
    asm volatile("mma.sync.aligned.m16n8k16.row.col.f32.f16.f16.f32 "
                 "{%0,%1,%2,%3}, {%4,%5,%6,%7}, {%8,%9}, {%0,%1,%2,%3};"
                 : "+f"(c[0]), "+f"(c[1]), "+f"(c[2]), "+f"(c[3])
                 : "r"(a[0]), "r"(a[1]), "r"(a[2]), "r"(a[3]), "r"(b[0]), "r"(b[1]));
}
__device__ __forceinline__ void tma2d(uint32_t dst, const CUtensorMap* map,
                                      int x, int y, uint32_t bar) {
    asm volatile("cp.async.bulk.tensor.2d.shared::cta.global.tile.mbarrier::complete_tx::bytes "
                 "[%0], [%1, {%2, %3}], [%4];"
                 :: "r"(dst), "l"(map), "r"(x), "r"(y), "r"(bar) : "memory");
}
#define MBARRIER_INIT(mbar, cnt) \
    asm volatile("mbarrier.init.shared.b64 [%0], %1;" \
        :: "r"((uint32_t)(mbar)), "r"((uint32_t)(cnt)) : "memory")
#define MBARRIER_EXPECT_TX(mbar, tx) \
    asm volatile("mbarrier.arrive.expect_tx.shared.b64 _, [%0], %1;" \
        :: "r"((uint32_t)(mbar)), "r"((uint32_t)(tx)) : "memory")
#define MBARRIER_WAIT_PARITY(mbar, par) do { \
    uint32_t _m = (uint32_t)(mbar); uint32_t _p = (uint32_t)(par); uint32_t _d; \
    asm volatile("{\n\t.reg .pred p;\n\t" \
        "mbarrier.try_wait.parity.acquire.cta.shared::cta.b64 p, [%1], %2;\n\t" \
        "selp.b32 %0, 1, 0, p;\n\t}" : "=r"(_d) : "r"(_m), "r"(_p) : "memory"); \
    if (!_d) { \
        asm volatile("{\n\t.reg .pred P1;\n\t" \
            "WL_%=:\n\t" \
            "mbarrier.try_wait.parity.acquire.cta.shared::cta.b64 P1, [%0], %1, 0x989680;\n\t" \
            "@P1 bra.uni WD_%=;\n\t" \
            "bra.uni WL_%=;\n\t" \
            "WD_%=:\n\t}" :: "r"(_m), "r"(_p) : "memory"); \
    } } while (0)

// Stage slot: [Ah | Al | Bh | Bl]; double-buffered; loads via TMA (off LSU).
template<int AT, int NB, int MT, int NT, int WMS>
__device__ __forceinline__ void mma_mainloop(
    const CUtensorMap* mAh, const CUtensorMap* mAl,
    const CUtensorMap* mBh, const CUtensorMap* mBl,
    int bm, int bn, char* smem, float (&acc)[MT][NT][4])
{
    constexpr int STB = 2 * AT * 4096 + 2 * NB * 128;
    constexpr int WNS = 8 / WMS;
    const int tid = threadIdx.x;
    const int wid = tid >> 5, l = tid & 31;
    const int wm = wid / WNS, wn = wid % WNS;
    uint32_t sbase = smem_u32(smem);
    uint32_t mb = sbase;             // 2 mbarriers @ +0, +8
    uint32_t stg = sbase + 1024;     // stage slots (1024-aligned)

#pragma unroll
    for (int mt = 0; mt < MT; ++mt)
#pragma unroll
        for (int nt = 0; nt < NT; ++nt)
#pragma unroll
            for (int e = 0; e < 4; ++e) acc[mt][nt][e] = 0.0f;

    if (tid == 0) { MBARRIER_INIT(mb, 1); MBARRIER_INIT(mb + 8, 1); }
    __syncthreads();

    auto issue = [&](int kc) {
        int s = kc & 1;
        uint32_t st = stg + s * STB;
        uint32_t bar = mb + s * 8;
        MBARRIER_EXPECT_TX(bar, STB);
        tma2d(st,                            mAh, kc * 64, bm, bar);
        tma2d(st + AT * 4096,                mAl, kc * 64, bm, bar);
        tma2d(st + 2 * AT * 4096,            mBh, kc * 64, bn, bar);
        tma2d(st + 2 * AT * 4096 + NB * 128, mBl, kc * 64, bn, bar);
    };
    if (tid == 0) { issue(0); issue(1); }

#pragma unroll 1
    for (int kc = 0; kc < KCH; ++kc) {
        int s = kc & 1;
        MBARRIER_WAIT_PARITY(mb + s * 8, (kc >> 1) & 1);

        uint32_t sAh = stg + s * STB;
        uint32_t sAl = sAh + AT * 4096;
        uint32_t sBh = sAh + 2 * AT * 4096;
        uint32_t sBl = sBh + NB * 128;
#pragma unroll
        for (int kt = 0; kt < 4; ++kt) {
            uint32_t afh[MT][4], afl[MT][4];
#pragma unroll
            for (int mt = 0; mt < MT; ++mt) {
                int row = wm * (MT * 16) + mt * 16 + (l & 15);
                int col = kt * 2 + (l >> 4);
                ldm_x4(afh[mt], sAh + SMOFF(row, col));
                ldm_x4(afl[mt], sAl + SMOFF(row, col));
            }
            uint32_t bh[NT][2], bl[NT][2];
            int g = l >> 3;
#pragma unroll
            for (int p = 0; p < NT / 2; ++p) {
                int nrow = wn * (NT * 8) + p * 16 + ((g >> 1) << 3) + (l & 7);
                int col = kt * 2 + (g & 1);
                uint32_t rr[4];
                ldm_x4(rr, sBh + SMOFF(nrow, col));
                bh[2 * p][0] = rr[0];     bh[2 * p][1] = rr[1];
                bh[2 * p + 1][0] = rr[2]; bh[2 * p + 1][1] = rr[3];
                ldm_x4(rr, sBl + SMOFF(nrow, col));
                bl[2 * p][0] = rr[0];     bl[2 * p][1] = rr[1];
                bl[2 * p + 1][0] = rr[2]; bl[2 * p + 1][1] = rr[3];
            }
#pragma unroll
            for (int mt = 0; mt < MT; ++mt)
#pragma unroll
                for (int nt = 0; nt < NT; ++nt) {
                    mma16816f(acc[mt][nt], afh[mt], bh[nt]);
                    mma16816f(acc[mt][nt], afh[mt], bl[nt]);
                    mma16816f(acc[mt][nt], afl[mt], bh[nt]);
                }
        }
        __syncthreads();           // all warps done with slot s
        if (tid == 0 && kc + 2 < KCH) issue(kc + 2);
    }
}

// ========== fused step-1 kernel: grid 2176 ==================================
// bids 0-127:    h2o(t-1)  [reads h2(t-1) splits: ready at launch; no waits]
// bids 128-2175: gh0(t)+gates1 (z=0) / gh1 -> bufB (z=1)
// gh z=0 epilogue waits (cheap, post-mainloop) for h2o(t-1) before reading g_c.
__global__ __launch_bounds__(256, 2)
void step1_kernel(const __grid_constant__ CUtensorMap mA0h, const __grid_constant__ CUtensorMap mA0l,
                  const __grid_constant__ CUtensorMap mB0h, const __grid_constant__ CUtensorMap mB0l,
                  const __grid_constant__ CUtensorMap mA1h, const __grid_constant__ CUtensorMap mA1l,
                  const __grid_constant__ CUtensorMap mB1h, const __grid_constant__ CUtensorMap mB1l,
                  const __grid_constant__ CUtensorMap oAh, const __grid_constant__ CUtensorMap oAl,
                  const __grid_constant__ CUtensorMap oBh, const __grid_constant__ CUtensorMap oBl,
                  float* __restrict__ h1O, __half* __restrict__ h1hiB, __half* __restrict__ h1loB,
                  float* __restrict__ out, int t)
{
    extern __shared__ char smem[];
    const int bid = blockIdx.x;
    const int tid = threadIdx.x;
    const int wid = tid >> 5, l = tid & 31;

    if (bid < 128) {
        // ---- h2o role for step t-1 (skip at t == 0) ----
        if (t == 0) return;
        const int tt = t - 1;
        const int bm = bid * 32;
        const int wm = wid >> 2, wn = wid & 3;   // 2x4 warp grid
        float acc[1][4][4];
        mma_mainloop<1, 128, 1, 4, 2>(&oAh, &oAl, &oBh, &oBl, bm, 0, smem, acc);
        __syncthreads();

        float* lg = (float*)(smem + 1024);
#pragma unroll
        for (int nt = 0; nt < 4; ++nt) {
            int rl = wm * 16 + (l >> 2);
            int cl = wn * 32 + nt * 8 + ((l & 3) << 1);
            lg[rl * 132 + cl]           = acc[0][nt][0];
            lg[rl * 132 + cl + 1]       = acc[0][nt][1];
            lg[(rl + 8) * 132 + cl]     = acc[0][nt][2];
            lg[(rl + 8) * 132 + cl + 1] = acc[0][nt][3];
        }
        __syncthreads();

        if (tid < 32) {
            int row = bm + tid;
            const float* oz = g_OutZ + (size_t)row * NCHAR;
            float* op = out + (size_t)row * (NSTEP * NCHAR) + tt * NCHAR;
            float best = -FLT_MAX;
            int bi = 0;
#pragma unroll 4
            for (int c = 0; c < NCHAR; ++c) {
                float v = lg[tid * 132 + c] + oz[c];
                op[c] = v;
                if (v > best) { best = v; bi = c; }
            }
            g_c[row] = bi;
        }
        __syncthreads();
        if (tid == 0) {
            __threadfence();
            atomicAdd(&g_sync[0], 1u);
        }
        return;
    }

    // ---- gh roles ----
    const int g = bid - 128;
    const int zz = g >> 10;               // 0: gh0+gates1, 1: gh1->bufB
    const int bn = (g & 31) * 96, bm = ((g >> 5) & 31) * 128;
    const int wm = wid >> 1, wn = wid & 1;   // 4x2 warp grid

    float acc[2][6][4];
    mma_mainloop<4, 96, 2, 6, 4>(zz ? &mA1h : &mA0h, zz ? &mA1l : &mA0l,
                                 zz ? &mB1h : &mB0h, zz ? &mB1l : &mB0l,
                                 bm, bn, smem, acc);

    if (zz == 1) {
#pragma unroll
        for (int mt = 0; mt < 2; ++mt)
#pragma unroll
            for (int nt = 0; nt < 6; ++nt) {
                int row = bm + wm * 32 + mt * 16 + (l >> 2);
                int col = bn + wn * 48 + nt * 8 + ((l & 3) << 1);
                float b0 = g_bhh1p[col], b1 = g_bhh1p[col + 1];
                *(float2*)&g_bufB[(size_t)row * NH3 + col] =
                    make_float2(acc[mt][nt][0] + b0, acc[mt][nt][1] + b1);
                *(float2*)&g_bufB[(size_t)(row + 8) * NH3 + col] =
                    make_float2(acc[mt][nt][2] + b0, acc[mt][nt][3] + b1);
            }
        return;
    }

    // z=0: stage C tile, wait for h2o(t-1) completion, then gates epilogue
    __syncthreads();
    float* Cs = (float*)(smem + 1024);
#pragma unroll
    for (int mt = 0; mt < 2; ++mt)
#pragma unroll
        for (int nt = 0; nt < 6; ++nt) {
            int r0 = wm * 32 + mt * 16 + (l >> 2);
            int c0 = wn * 48 + nt * 8 + ((l & 3) << 1);
            Cs[r0 * 100 + c0]           = acc[mt][nt][0];
            Cs[r0 * 100 + c0 + 1]       = acc[mt][nt][1];
            Cs[(r0 + 8) * 100 + c0]     = acc[mt][nt][2];
            Cs[(r0 + 8) * 100 + c0 + 1] = acc[mt][nt][3];
        }
    if (tid == 0) {
        unsigned target = 128u * (unsigned)t;   // h2o(0..t-1) all done
        while (atomicAdd(&g_sync[0], 0u) < target) __nanosleep(100);
    }
    __syncthreads();

    const int ul = l;
    const int u  = bn / 3 + ul;
    float bh0 = g_bhh0p[bn + ul];
    float bh1 = g_bhh0p[bn + 32 + ul];
    float bh2 = g_bhh0p[bn + 64 + ul];
#pragma unroll 2
    for (int i = 0; i < 16; ++i) {
        int rb = wid * 16 + i;
        int b = bm + rb;
        float ghr = Cs[rb * 100 + ul] + bh0;
        float ghz = Cs[rb * 100 + 32 + ul] + bh1;
        float ghn = Cs[rb * 100 + 64 + ul] + bh2;
        const float* gp = g_Z0 + (size_t)b * NH3 + bn;
        int cb = g_c[b];
        const float* tp = g_T0 + (size_t)cb * NH3 + bn;
        float gir = gp[ul] + tp[ul];
        float giz = gp[32 + ul] + tp[32 + ul];
        float gin = gp[64 + ul] + tp[64 + ul];
        float r  = 1.0f / (1.0f + expf(-(gir + ghr)));
        float zg = 1.0f / (1.0f + expf(-(giz + ghz)));
        float nn = tanhf(gin + r * ghn);
        size_t hidx = (size_t)b * NH + u;
        float hv = h1O[hidx];
        float hn2 = (1.0f - zg) * nn + zg * hv;
        h1O[hidx] = hn2;
        __half hb = __float2half_rn(hn2);
        h1hiB[hidx] = hb;
        h1loB[hidx] = __float2half_rn(hn2 - __half2float(hb));
    }
}

// ===================== gi kernel: grid (32,32), fused gates2 ================
__global__ __launch_bounds__(256, 2)
void gi_kernel(const __grid_constant__ CUtensorMap mAh, const __grid_constant__ CUtensorMap mAl,
               const __grid_constant__ CUtensorMap mBh, const __grid_constant__ CUtensorMap mBl)
{
    extern __shared__ char smem[];
    const int bn = blockIdx.x * 96, bm = blockIdx.y * 128;
    const int tid = threadIdx.x;
    const int wid = tid >> 5, l = tid & 31;
    const int wm = wid >> 1, wn = wid & 1;
    float acc[2][6][4];
    mma_mainloop<4, 96, 2, 6, 4>(&mAh, &mAl, &mBh, &mBl, bm, bn, smem, acc);

    __syncthreads();
    float* Cs = (float*)(smem + 1024);
#pragma unroll
    for (int mt = 0; mt < 2; ++mt)
#pragma unroll
        for (int nt = 0; nt < 6; ++nt) {
            int r0 = wm * 32 + mt * 16 + (l >> 2);
            int c0 = wn * 48 + nt * 8 + ((l & 3) << 1);
            Cs[r0 * 100 + c0]           = acc[mt][nt][0];
            Cs[r0 * 100 + c0 + 1]       = acc[mt][nt][1];
            Cs[(r0 + 8) * 100 + c0]     = acc[mt][nt][2];
            Cs[(r0 + 8) * 100 + c0 + 1] = acc[mt][nt][3];
        }
    __syncthreads();

    const int ul = l;
    const int u  = bn / 3 + ul;
    float bi0 = g_bih1p[bn + ul];
    float bi1 = g_bih1p[bn + 32 + ul];
    float bi2 = g_bih1p[bn + 64 + ul];
#pragma unroll 2
    for (int i = 0; i < 16; ++i) {
        int rb = wid * 16 + i;
        int b = bm + rb;
        float gir = Cs[rb * 100 + ul] + bi0;
        float giz = Cs[rb * 100 + 32 + ul] + bi1;
        float gin = Cs[rb * 100 + 64 + ul] + bi2;
        const float* gp = g_bufB + (size_t)b * NH3 + bn;
        float ghr = gp[ul], ghz = gp[32 + ul], ghn = gp[64 + ul];
        float r  = 1.0f / (1.0f + expf(-(gir + ghr)));
        float zg = 1.0f / (1.0f + expf(-(giz + ghz)));
        float nn = tanhf(gin + r * ghn);
        size_t hidx = (size_t)b * NH + u;
        float hv = g_h2[hidx];
        float hn2 = (1.0f - zg) * nn + zg * hv;
        g_h2[hidx] = hn2;
        __half hb = __float2half_rn(hn2);
        g_h2hi[hidx] = hb;
        g_h2lo[hidx] = __float2half_rn(hn2 - __half2float(hb));
    }
}

// ===================== host: tensor map encoding ============================
typedef CUresult (*encode_fn_t)(CUtensorMap*, CUtensorMapDataType, cuuint32_t, void*,
                                const cuuint64_t*, const cuuint64_t*,
                                const cuuint32_t*, const cuuint32_t*,
                                CUtensorMapInterleave, CUtensorMapSwizzle,
                                CUtensorMapL2promotion, CUtensorMapFloatOOBfill);

static encode_fn_t get_encoder() {
    static encode_fn_t fp = nullptr;
    if (!fp) {
        void* p = nullptr;
        cudaDriverEntryPointQueryResult st;
        cudaGetDriverEntryPoint("cuTensorMapEncodeTiled", &p, cudaEnableDefault, &st);
        fp = (encode_fn_t)p;
    }
    return fp;
}

static void make_map(CUtensorMap* m, void* base, uint64_t nrows, uint32_t box_rows) {
    cuuint64_t dims[2]    = {1024, nrows};
    cuuint64_t strides[1] = {2048};            // row pitch bytes (fp16 x 1024)
    cuuint32_t box[2]     = {64, box_rows};    // 64 fp16 = 128B (SW128 atom)
    cuuint32_t es[2]      = {1, 1};
    get_encoder()(m, CU_TENSOR_MAP_DATA_TYPE_UINT16, 2, base, dims, strides, box, es,
                  CU_TENSOR_MAP_INTERLEAVE_NONE, CU_TENSOR_MAP_SWIZZLE_128B,
                  CU_TENSOR_MAP_L2_PROMOTION_L2_128B, CU_TENSOR_MAP_FLOAT_OOB_FILL_NONE);
}

// ===================== launch ===============================================
extern "C" void kernel_launch(void* const* d_in, const int* in_sizes, int n_in,
                              void* d_out, int out_size)
{
    const float* z       = (const float*)d_in[0];
    const float* embed_w = (const float*)d_in[1];
    const float* z2h_w   = (const float*)d_in[2];
    const float* z2h_b   = (const float*)d_in[3];
    const float* w_ih0   = (const float*)d_in[4];
    const float* w_hh0   = (const float*)d_in[5];
    const float* b_ih0   = (const float*)d_in[6];
    const float* b_hh0   = (const float*)d_in[7];
    const float* w_ih1   = (const float*)d_in[8];
    const float* w_hh1   = (const float*)d_in[9];
    const float* b_ih1   = (const float*)d_in[10];
    const float* b_hh1   = (const float*)d_in[11];
    const float* h2o_w   = (const float*)d_in[12];
    const float* h2o_b   = (const float*)d_in[13];
    float* out = (float*)d_out;

    __half *h1hi0, *h1lo0, *h2hip, *h2lop;
    __half *Whh0h, *Whh0l, *Whh1h, *Whh1l, *Wih1h, *Wih1l, *Wouth, *Woutl;
    float* h1p;
    cudaGetSymbolAddress((void**)&h1hi0, g_h1hi);
    cudaGetSymbolAddress((void**)&h1lo0, g_h1lo);
    cudaGetSymbolAddress((void**)&h2hip, g_h2hi);
    cudaGetSymbolAddress((void**)&h2lop, g_h2lo);
    cudaGetSymbolAddress((void**)&Whh0h, g_Whh0hi);
    cudaGetSymbolAddress((void**)&Whh0l, g_Whh0lo);
    cudaGetSymbolAddress((void**)&Whh1h, g_Whh1hi);
    cudaGetSymbolAddress((void**)&Whh1l, g_Whh1lo);
    cudaGetSymbolAddress((void**)&Wih1h, g_Wih1hi);
    cudaGetSymbolAddress((void**)&Wih1l, g_Wih1lo);
    cudaGetSymbolAddress((void**)&Wouth, g_Wouthi);
    cudaGetSymbolAddress((void**)&Woutl, g_Woutlo);
    cudaGetSymbolAddress((void**)&h1p, g_h1);
    __half* h1hi1 = h1hi0 + (size_t)BATCH * NH;
    __half* h1lo1 = h1lo0 + (size_t)BATCH * NH;

    // tensor maps (host-side encode; pure CPU, capture-safe)
    static CUtensorMap mh1h[2], mh1l[2], mh2h, mh2l, mh2h32, mh2l32;
    static CUtensorMap mWhh0h, mWhh0l, mWhh1h, mWhh1l, mWih1h, mWih1l, mWouth, mWoutl;
    make_map(&mh1h[0], h1hi0, BATCH, 128);
    make_map(&mh1l[0], h1lo0, BATCH, 128);
    make_map(&mh1h[1], h1hi1, BATCH, 128);
    make_map(&mh1l[1], h1lo1, BATCH, 128);
    make_map(&mh2h,    h2hip, BATCH, 128);
    make_map(&mh2l,    h2lop, BATCH, 128);
    make_map(&mh2h32,  h2hip, BATCH, 32);
    make_map(&mh2l32,  h2lop, BATCH, 32);
    make_map(&mWhh0h,  Whh0h, NH3, 96);
    make_map(&mWhh0l,  Whh0l, NH3, 96);
    make_map(&mWhh1h,  Whh1h, NH3, 96);
    make_map(&mWhh1l,  Whh1l, NH3, 96);
    make_map(&mWih1h,  Wih1h, NH3, 96);
    make_map(&mWih1l,  Wih1l, NH3, 96);
    make_map(&mWouth,  Wouth, NCHAR, 128);
    make_map(&mWoutl,  Woutl, NCHAR, 128);

    const int smem_big = 1024 + 2 * (2 * 4 * 4096 + 2 * 96 * 128);   // 115712
    cudaFuncSetAttribute(step1_kernel, cudaFuncAttributeMaxDynamicSharedMemorySize, smem_big);
    cudaFuncSetAttribute(gi_kernel, cudaFuncAttributeMaxDynamicSharedMemorySize, smem_big);

    // ---- precompute: 3 launches ----
    prep0_kernel<<<(NCHAR * NH + 255) / 256, 256>>>(embed_w, b_ih0, b_hh0, b_ih1, b_hh1);
    prep_gemms<<<dim3(24, 32, 4), 256>>>(z, w_ih0, z2h_w, z2h_b, h2o_w, h2o_b);
    splits_kernel<<<dim3(BATCH * NH / 256, 1, 5), 256>>>(w_hh0, w_ih1, w_hh1, h2o_w);

    // ---- 64 steps, 2 launches each + final h2o(63) ----
    for (int t = 0; t < NSTEP; ++t) {
        int p = t & 1;
        __half* whi = p ? h1hi0 : h1hi1;
        __half* wlo = p ? h1lo0 : h1lo1;

        // [h2o(t-1)] + gh0(t)+gates1 -> h1 + gh1 -> bufB
        step1_kernel<<<2176, 256, smem_big>>>(
            mh1h[p], mh1l[p], mWhh0h, mWhh0l,
            mh2h, mh2l, mWhh1h, mWhh1l,
            mh2h32, mh2l32, mWouth, mWoutl,
            h1p, whi, wlo, out, t);
        // gi(t) + gates2 -> h2, splits
        gi_kernel<<<dim3(32, 32), 256, smem_big>>>(
            mh1h[1 - p], mh1l[1 - p], mWih1h, mWih1l);
    }
    // final h2o(63): grid 128 (h2o role only), t = NSTEP
    step1_kernel<<<128, 256, smem_big>>>(
        mh1h[0], mh1l[0], mWhh0h, mWhh0l,
        mh2h, mh2l, mWhh1h, mWhh1l,
        mh2h32, mh2l32, mWouth, mWoutl,
        h1p, h1hi0, h1lo0, out, NSTEP);
}